// round 11
// baseline (speedup 1.0000x reference)
#include <cuda_runtime.h>
#include <cuda_bf16.h>
#include <math.h>
#include <float.h>

#define N_NODES 50000
#define N_EDGES 1600000
#define N_MSG   (N_EDGES + N_NODES)
#define C_OUT   40

// ---------------- scratch (static device globals; no allocation) ----------------
__device__ __align__(256) unsigned int g_agg_u[N_NODES * 64]; // mapped-uint segment-max
__device__ __align__(256) float g_g1 [N_NODES * 128];
__device__ __align__(256) int g_deg [N_NODES];
__device__ __align__(256) int g_cur [N_NODES];
__device__ __align__(256) int g_srcs[N_MSG];
__device__ __align__(256) int g_dsts[N_MSG];

// ---------------- helpers ----------------
__device__ __forceinline__ unsigned int fmap(float v) {
    unsigned int k = __float_as_uint(v);
    return ((int)k < 0) ? ~k : (k | 0x80000000u);
}
__device__ __forceinline__ float funmap(unsigned int k) {
    return (k & 0x80000000u) ? __uint_as_float(k & 0x7FFFFFFFu)
                             : __uint_as_float(~k);
}
// tf32 mma reads only bits [31:13]; raw f32 bits == RZ-truncated tf32.
__device__ __forceinline__ void mma_tf32(float (&c)[4],
                                         unsigned int a0, unsigned int a1,
                                         unsigned int a2, unsigned int a3,
                                         unsigned int b0, unsigned int b1) {
    asm volatile(
        "mma.sync.aligned.m16n8k8.row.col.f32.tf32.tf32.f32 "
        "{%0,%1,%2,%3}, {%4,%5,%6,%7}, {%8,%9}, {%0,%1,%2,%3};"
        : "+f"(c[0]), "+f"(c[1]), "+f"(c[2]), "+f"(c[3])
        : "r"(a0), "r"(a1), "r"(a2), "r"(a3), "r"(b0), "r"(b1));
}

// ---------------- CSR build: count / scan / scatter ----------------
__global__ __launch_bounds__(256) void k_count(const int* __restrict__ ei) {
    int m = blockIdx.x * blockDim.x + threadIdx.x;
    if (m >= N_MSG) return;
    int dst = (m < N_EDGES) ? ei[N_EDGES + m] : (m - N_EDGES);
    atomicAdd(&g_deg[dst], 1);
}

__global__ __launch_bounds__(1024) void k_scan() {   // single block
    __shared__ int ssum[1024];
    const int T = 1024, CH = (N_NODES + T - 1) / T;  // 49
    int t = threadIdx.x;
    int base = t * CH;
    int s = 0;
    for (int i = 0; i < CH; i++) {
        int idx = base + i;
        if (idx < N_NODES) s += g_deg[idx];
    }
    ssum[t] = s;
    __syncthreads();
    // Hillis-Steele inclusive scan
    for (int off = 1; off < T; off <<= 1) {
        int v = (t >= off) ? ssum[t - off] : 0;
        __syncthreads();
        ssum[t] += v;
        __syncthreads();
    }
    int run = (t > 0) ? ssum[t - 1] : 0;   // exclusive prefix of chunk
    for (int i = 0; i < CH; i++) {
        int idx = base + i;
        if (idx < N_NODES) {
            int d = g_deg[idx];
            g_cur[idx] = run;
            run += d;
        }
    }
}

__global__ __launch_bounds__(256) void k_scatter(const int* __restrict__ ei) {
    int m = blockIdx.x * blockDim.x + threadIdx.x;
    if (m >= N_MSG) return;
    int src, dst;
    if (m < N_EDGES) { src = ei[m]; dst = ei[N_EDGES + m]; }
    else             { src = dst = m - N_EDGES; }
    int slot = atomicAdd(&g_cur[dst], 1);
    g_srcs[slot] = src;
    g_dsts[slot] = dst;
}

// ---------------- edge MLP on sorted messages + smem segment-max ----------------
// dynamic smem layout (words):
//   [0, 8704)      h1s [k=64][H1S=136]  ALIASED with hS [r=128][HS=68] (both 8704)
//   [8704, 13312)  sW2t [k=64][W2S=72]
//   [13312, 13696) sW1 [6*64]
//   [13696, 13760) sb1
//   [13760, 13824) sb2
//   [13824, 13952) sdst (int)
#define ES_H1   0
#define ES_W2   8704
#define ES_W1   13312
#define ES_B1   13696
#define ES_B2   13760
#define ES_DST  13824
#define ES_WORDS 13952
#define H1S 136
#define HS  68
#define W2S 72
__global__ __launch_bounds__(256) void k_edge_csr(
    const float* __restrict__ x,          // [N,3]
    const float* __restrict__ pos,        // [N,3]
    const float* __restrict__ W1,         // [6,64]
    const float* __restrict__ b1,         // [64]
    const float* __restrict__ W2,         // [64,64]
    const float* __restrict__ b2)         // [64]
{
    extern __shared__ unsigned int sm[];
    float* sW1 = (float*)(sm + ES_W1);
    float* sb1 = (float*)(sm + ES_B1);
    float* sb2 = (float*)(sm + ES_B2);
    int*   sdst = (int*)(sm + ES_DST);

    const int tid  = threadIdx.x;
    const int lane = tid & 31;
    const int warp = tid >> 5;

    for (int i = tid; i < 6 * 64; i += 256) sW1[i] = W1[i];
    if (tid < 64) { sb1[tid] = b1[tid]; sb2[tid] = b2[tid]; }
    for (int i = tid; i < 64 * 64; i += 256) {
        int k = i >> 6, n = i & 63;
        sm[ES_W2 + k * W2S + n] = __float_as_uint(W2[i]);
    }

    const int s0 = blockIdx.x * 128;
    const int ml = tid & 127;
    const int kh = tid >> 7;
    const int slot = s0 + ml;

    int src = 0, dst = -1;
    if (slot < N_MSG) { src = g_srcs[slot]; dst = g_dsts[slot]; }
    if (kh == 0) sdst[ml] = dst;

    float in[6];
    if (dst >= 0) {
        in[0] = x[src * 3 + 0];
        in[1] = x[src * 3 + 1];
        in[2] = x[src * 3 + 2];
        in[3] = pos[src * 3 + 0] - pos[dst * 3 + 0];
        in[4] = pos[src * 3 + 1] - pos[dst * 3 + 1];
        in[5] = pos[src * 3 + 2] - pos[dst * 3 + 2];
    } else {
        #pragma unroll
        for (int i = 0; i < 6; i++) in[i] = 0.0f;
    }
    __syncthreads();   // weight staging + sdst done

    // layer 1
    #pragma unroll
    for (int j = 0; j < 32; j++) {
        int k = kh * 32 + j;
        float h = sb1[k];
        #pragma unroll
        for (int i = 0; i < 6; i++) h = fmaf(in[i], sW1[i * 64 + k], h);
        h = fmaxf(h, 0.0f);
        sm[ES_H1 + k * H1S + ml] = __float_as_uint(h);
    }
    __syncthreads();

    // layer 2 mma: warp w -> messages [w*16, w*16+16), 64 channels
    const int g  = lane >> 2;
    const int tg = lane & 3;
    const int mrow = warp * 16;

    float c[8][4];
    #pragma unroll
    for (int nt = 0; nt < 8; nt++)
        #pragma unroll
        for (int q = 0; q < 4; q++) c[nt][q] = 0.0f;

    #pragma unroll
    for (int ks = 0; ks < 8; ks++) {
        const int k0 = ks * 8;
        unsigned int a0 = sm[ES_H1 + (k0 + tg    ) * H1S + mrow + g    ];
        unsigned int a1 = sm[ES_H1 + (k0 + tg    ) * H1S + mrow + g + 8];
        unsigned int a2 = sm[ES_H1 + (k0 + tg + 4) * H1S + mrow + g    ];
        unsigned int a3 = sm[ES_H1 + (k0 + tg + 4) * H1S + mrow + g + 8];
        #pragma unroll
        for (int nt = 0; nt < 8; nt++) {
            unsigned int b0 = sm[ES_W2 + (k0 + tg    ) * W2S + nt * 8 + g];
            unsigned int b1 = sm[ES_W2 + (k0 + tg + 4) * W2S + nt * 8 + g];
            mma_tf32(c[nt], a0, a1, a2, a3, b0, b1);
        }
    }
    __syncthreads();   // everyone done reading h1s; safe to alias as hS

    // write h tile (+b2) into hS [r][HS]
    #pragma unroll
    for (int nt = 0; nt < 8; nt++) {
        int ch = nt * 8 + 2 * tg;
        float bv0 = sb2[ch], bv1 = sb2[ch + 1];
        int r0 = mrow + g, r1 = mrow + g + 8;
        sm[ES_H1 + r0 * HS + ch    ] = __float_as_uint(c[nt][0] + bv0);
        sm[ES_H1 + r0 * HS + ch + 1] = __float_as_uint(c[nt][1] + bv1);
        sm[ES_H1 + r1 * HS + ch    ] = __float_as_uint(c[nt][2] + bv0);
        sm[ES_H1 + r1 * HS + ch + 1] = __float_as_uint(c[nt][3] + bv1);
    }
    __syncthreads();

    // segmented max flush: thread = (channel, 32-row chunk); dsts sorted within tile
    {
        int ch = tid & 63;
        int rc = tid >> 6;          // 0..3
        int rbeg = rc * 32, rend = rbeg + 32;
        int cur = -1;
        float mx = 0.0f;
        for (int r = rbeg; r < rend; r++) {
            int d = sdst[r];
            if (d < 0) break;       // padding only at the tail of the last tile
            float v = __uint_as_float(sm[ES_H1 + r * HS + ch]);
            if (d != cur) {
                if (cur >= 0) atomicMax(g_agg_u + (size_t)cur * 64 + ch, fmap(mx));
                cur = d; mx = v;
            } else {
                mx = fmaxf(mx, v);
            }
        }
        if (cur >= 0) atomicMax(g_agg_u + (size_t)cur * 64 + ch, fmap(mx));
    }
}

// ---------------- proven fp32 register-tiled GEMM (64 -> 128 layer) ----------------
template<int K_TOT, int NOUT, bool RELU_OUT, bool UNMAP>
__global__ __launch_bounds__(256) void k_mlp_gemm(
    const void* __restrict__ Av,
    const float* __restrict__ W,
    const float* __restrict__ b,
    float* __restrict__ C,
    int nrows)
{
    __shared__ float As[32][129];
    __shared__ float Bs[32][64];

    const int tid = threadIdx.x;
    const int n0 = blockIdx.x * 128;
    const int o0 = blockIdx.y * 64;
    const int ot = tid & 15;
    const int nt = tid >> 4;

    const float* Af = (const float*)Av;
    const unsigned int* Au = (const unsigned int*)Av;

    float acc[8][4];
    #pragma unroll
    for (int j = 0; j < 8; j++)
        #pragma unroll
        for (int q = 0; q < 4; q++) acc[j][q] = 0.0f;

    const int kk = tid & 31;
    const int nr = tid >> 5;
    const int oo = tid & 63;
    const int kb = tid >> 6;

    for (int k0 = 0; k0 < K_TOT; k0 += 32) {
        #pragma unroll
        for (int jj = 0; jj < 16; jj++) {
            int n = nr * 16 + jj;
            int row = n0 + n;
            float v = 0.0f;
            if (row < nrows) {
                size_t idx = (size_t)row * K_TOT + k0 + kk;
                v = UNMAP ? funmap(Au[idx]) : Af[idx];
            }
            As[kk][n] = v;
        }
        #pragma unroll
        for (int jj = 0; jj < 8; jj++) {
            int k = kb * 8 + jj;
            Bs[k][oo] = W[(size_t)(k0 + k) * NOUT + o0 + oo];
        }
        __syncthreads();

        #pragma unroll
        for (int k = 0; k < 32; k++) {
            float4 wv = *(const float4*)&Bs[k][ot * 4];
            float av[8];
            #pragma unroll
            for (int j = 0; j < 8; j++) av[j] = As[k][nt * 8 + j];
            #pragma unroll
            for (int j = 0; j < 8; j++) {
                acc[j][0] = fmaf(av[j], wv.x, acc[j][0]);
                acc[j][1] = fmaf(av[j], wv.y, acc[j][1]);
                acc[j][2] = fmaf(av[j], wv.z, acc[j][2]);
                acc[j][3] = fmaf(av[j], wv.w, acc[j][3]);
            }
        }
        __syncthreads();
    }

    float bias0 = b[o0 + ot * 4 + 0];
    float bias1 = b[o0 + ot * 4 + 1];
    float bias2 = b[o0 + ot * 4 + 2];
    float bias3 = b[o0 + ot * 4 + 3];
    #pragma unroll
    for (int j = 0; j < 8; j++) {
        int row = n0 + nt * 8 + j;
        if (row >= nrows) continue;
        float4 v;
        v.x = acc[j][0] + bias0;
        v.y = acc[j][1] + bias1;
        v.z = acc[j][2] + bias2;
        v.w = acc[j][3] + bias3;
        if (RELU_OUT) {
            v.x = fmaxf(v.x, 0.0f); v.y = fmaxf(v.y, 0.0f);
            v.z = fmaxf(v.z, 0.0f); v.w = fmaxf(v.w, 0.0f);
        }
        *(float4*)&C[(size_t)row * NOUT + o0 + ot * 4] = v;
    }
}

// ---------------- fused: relu(g1@W4+b4)@W5+b5 -> relu -> fc -> log_softmax ----------------
#define FS_G1 0                     // [128m][132]
#define FS_B  16896                 // W4 chunk [128k][136] / W5 chunk [128k][72] / Wf [64*40]
#define FS_T  34304                 // [128m][132] relu tile / g3 tile [128m][68]
#define FS_B4 51200                 // [128] / bf [40]
#define FS_B5 51328                 // [64]
#define FS_WORDS 51392              // 205,568 bytes dynamic smem

__global__ __launch_bounds__(256) void k_fused_mid(
    const float* __restrict__ A,    // g1 [nrows,128]
    const float* __restrict__ W4,   // [128,1024]
    const float* __restrict__ b4,   // [1024]
    const float* __restrict__ W5,   // [1024,64]
    const float* __restrict__ b5,   // [64]
    const float* __restrict__ Wf,   // [64,40]
    const float* __restrict__ bf,   // [40]
    float* __restrict__ out,        // [nrows,40]
    int nrows)
{
    extern __shared__ unsigned int sm[];
    const int tid  = threadIdx.x;
    const int lane = tid & 31;
    const int warp = tid >> 5;
    const int wm   = warp >> 1;
    const int wn   = warp & 1;
    const int g    = lane >> 2;
    const int tg   = lane & 3;
    const int mrow = wm * 32;
    const int n0   = blockIdx.x * 128;

    #pragma unroll
    for (int i = 0; i < 16; i++) {
        int idx = tid + i * 256;
        int mm = idx >> 5, q = idx & 31;
        int row = n0 + mm;
        uint4 v = make_uint4(0u, 0u, 0u, 0u);
        if (row < nrows) v = *(const uint4*)&A[(size_t)row * 128 + q * 4];
        *(uint4*)&sm[FS_G1 + mm * 132 + q * 4] = v;
    }
    if (tid < 64) sm[FS_B5 + tid] = __float_as_uint(b5[tid]);

    float acc2[2][4][4];
    #pragma unroll
    for (int mt = 0; mt < 2; mt++)
        #pragma unroll
        for (int nt = 0; nt < 4; nt++)
            #pragma unroll
            for (int q = 0; q < 4; q++) acc2[mt][nt][q] = 0.0f;

    for (int cch = 0; cch < 8; cch++) {
        __syncthreads();
        #pragma unroll
        for (int i = 0; i < 16; i++) {
            int idx = tid + i * 256;
            int k = idx >> 5, q = idx & 31;
            *(uint4*)&sm[FS_B + k * 136 + q * 4] =
                *(const uint4*)&W4[(size_t)k * 1024 + cch * 128 + q * 4];
        }
        if (tid < 128) sm[FS_B4 + tid] = __float_as_uint(b4[cch * 128 + tid]);
        __syncthreads();

        float acc1[2][8][4];
        #pragma unroll
        for (int mt = 0; mt < 2; mt++)
            #pragma unroll
            for (int nt = 0; nt < 8; nt++)
                #pragma unroll
                for (int q = 0; q < 4; q++) acc1[mt][nt][q] = 0.0f;

        #pragma unroll
        for (int ks = 0; ks < 16; ks++) {
            const int k0 = ks * 8;
            unsigned int a[2][4];
            #pragma unroll
            for (int mt = 0; mt < 2; mt++) {
                int mr = mrow + mt * 16;
                a[mt][0] = sm[FS_G1 + (mr + g    ) * 132 + k0 + tg    ];
                a[mt][1] = sm[FS_G1 + (mr + g + 8) * 132 + k0 + tg    ];
                a[mt][2] = sm[FS_G1 + (mr + g    ) * 132 + k0 + tg + 4];
                a[mt][3] = sm[FS_G1 + (mr + g + 8) * 132 + k0 + tg + 4];
            }
            #pragma unroll
            for (int nt = 0; nt < 8; nt++) {
                int nc = wn * 64 + nt * 8 + g;
                unsigned int b0 = sm[FS_B + (k0 + tg    ) * 136 + nc];
                unsigned int b1 = sm[FS_B + (k0 + tg + 4) * 136 + nc];
                #pragma unroll
                for (int mt = 0; mt < 2; mt++)
                    mma_tf32(acc1[mt][nt], a[mt][0], a[mt][1], a[mt][2], a[mt][3], b0, b1);
            }
        }
        __syncthreads();

        #pragma unroll
        for (int nt = 0; nt < 8; nt++) {
            int col = wn * 64 + nt * 8 + 2 * tg;
            float bv0 = __uint_as_float(sm[FS_B4 + col]);
            float bv1 = __uint_as_float(sm[FS_B4 + col + 1]);
            #pragma unroll
            for (int mt = 0; mt < 2; mt++) {
                int r0 = mrow + mt * 16 + g;
                int r1 = r0 + 8;
                sm[FS_T + r0 * 132 + col    ] = __float_as_uint(fmaxf(acc1[mt][nt][0] + bv0, 0.0f));
                sm[FS_T + r0 * 132 + col + 1] = __float_as_uint(fmaxf(acc1[mt][nt][1] + bv1, 0.0f));
                sm[FS_T + r1 * 132 + col    ] = __float_as_uint(fmaxf(acc1[mt][nt][2] + bv0, 0.0f));
                sm[FS_T + r1 * 132 + col + 1] = __float_as_uint(fmaxf(acc1[mt][nt][3] + bv1, 0.0f));
            }
        }
        #pragma unroll
        for (int i = 0; i < 8; i++) {
            int idx = tid + i * 256;
            int k = idx >> 4, q = idx & 15;
            *(uint4*)&sm[FS_B + k * 72 + q * 4] =
                *(const uint4*)&W5[(size_t)(cch * 128 + k) * 64 + q * 4];
        }
        __syncthreads();

        #pragma unroll
        for (int ks = 0; ks < 16; ks++) {
            const int k0 = ks * 8;
            unsigned int a[2][4];
            #pragma unroll
            for (int mt = 0; mt < 2; mt++) {
                int mr = mrow + mt * 16;
                a[mt][0] = sm[FS_T + (mr + g    ) * 132 + k0 + tg    ];
                a[mt][1] = sm[FS_T + (mr + g + 8) * 132 + k0 + tg    ];
                a[mt][2] = sm[FS_T + (mr + g    ) * 132 + k0 + tg + 4];
                a[mt][3] = sm[FS_T + (mr + g + 8) * 132 + k0 + tg + 4];
            }
            #pragma unroll
            for (int nt = 0; nt < 4; nt++) {
                int nc = wn * 32 + nt * 8 + g;
                unsigned int b0 = sm[FS_B + (k0 + tg    ) * 72 + nc];
                unsigned int b1 = sm[FS_B + (k0 + tg + 4) * 72 + nc];
                #pragma unroll
                for (int mt = 0; mt < 2; mt++)
                    mma_tf32(acc2[mt][nt], a[mt][0], a[mt][1], a[mt][2], a[mt][3], b0, b1);
            }
        }
    }
    __syncthreads();   // done with FS_B / FS_T as GEMM buffers

    // load Wf/bf; stage g3 tile (+b5, NO relu) into FS_T stride 68
    for (int i = tid; i < 64 * 40; i += 256) sm[FS_B + i] = __float_as_uint(Wf[i]);
    if (tid < 40) sm[FS_B4 + tid] = __float_as_uint(bf[tid]);
    #pragma unroll
    for (int nt = 0; nt < 4; nt++) {
        int col = wn * 32 + nt * 8 + 2 * tg;
        float bv0 = __uint_as_float(sm[FS_B5 + col]);
        float bv1 = __uint_as_float(sm[FS_B5 + col + 1]);
        #pragma unroll
        for (int mt = 0; mt < 2; mt++) {
            int r0 = mrow + mt * 16 + g;
            int r1 = r0 + 8;
            sm[FS_T + r0 * 68 + col    ] = __float_as_uint(acc2[mt][nt][0] + bv0);
            sm[FS_T + r0 * 68 + col + 1] = __float_as_uint(acc2[mt][nt][1] + bv1);
            sm[FS_T + r1 * 68 + col    ] = __float_as_uint(acc2[mt][nt][2] + bv0);
            sm[FS_T + r1 * 68 + col + 1] = __float_as_uint(acc2[mt][nt][3] + bv1);
        }
    }
    __syncthreads();

    // fc + log_softmax: each warp handles 16 nodes
    for (int j = 0; j < 16; j++) {
        int nl = warp * 16 + j;
        int node = n0 + nl;
        if (node >= nrows) break;
        float v0 = __uint_as_float(sm[FS_B4 + lane]);
        float v1 = (lane < 8) ? __uint_as_float(sm[FS_B4 + lane + 32]) : -FLT_MAX;
        #pragma unroll
        for (int k = 0; k < 64; k++) {
            float a = fmaxf(__uint_as_float(sm[FS_T + nl * 68 + k]), 0.0f);
            float w0 = __uint_as_float(sm[FS_B + k * 40 + lane]);
            v0 = fmaf(a, w0, v0);
            if (lane < 8) {
                float w1 = __uint_as_float(sm[FS_B + k * 40 + lane + 32]);
                v1 = fmaf(a, w1, v1);
            }
        }
        float mx = fmaxf(v0, v1);
        #pragma unroll
        for (int off = 16; off > 0; off >>= 1)
            mx = fmaxf(mx, __shfl_xor_sync(0xFFFFFFFFu, mx, off));
        float s = __expf(v0 - mx) + ((lane < 8) ? __expf(v1 - mx) : 0.0f);
        #pragma unroll
        for (int off = 16; off > 0; off >>= 1)
            s += __shfl_xor_sync(0xFFFFFFFFu, s, off);
        float ls = __logf(s);
        float* op = out + (size_t)node * C_OUT;
        op[lane] = v0 - mx - ls;
        if (lane < 8) op[lane + 32] = v1 - mx - ls;
    }
}

// ---------------- launcher ----------------
extern "C" void kernel_launch(void* const* d_in, const int* in_sizes, int n_in,
                              void* d_out, int out_size) {
    const float* x   = (const float*)d_in[0];
    const float* pos = (const float*)d_in[1];
    const int*   ei  = (const int*)d_in[2];
    const float* W1 = (const float*)d_in[3];
    const float* b1 = (const float*)d_in[4];
    const float* W2 = (const float*)d_in[5];
    const float* b2 = (const float*)d_in[6];
    const float* W3 = (const float*)d_in[7];
    const float* b3 = (const float*)d_in[8];
    const float* W4 = (const float*)d_in[9];
    const float* b4 = (const float*)d_in[10];
    const float* W5 = (const float*)d_in[11];
    const float* b5 = (const float*)d_in[12];
    const float* Wf = (const float*)d_in[13];
    const float* bf = (const float*)d_in[14];
    float* out = (float*)d_out;

    void* aggp = nullptr; void* g1 = nullptr; void* degp = nullptr;
    cudaGetSymbolAddress(&aggp, g_agg_u);
    cudaGetSymbolAddress(&g1, g_g1);
    cudaGetSymbolAddress(&degp, g_deg);

    cudaFuncSetAttribute(k_edge_csr, cudaFuncAttributeMaxDynamicSharedMemorySize,
                         ES_WORDS * 4);
    cudaFuncSetAttribute(k_fused_mid, cudaFuncAttributeMaxDynamicSharedMemorySize,
                         FS_WORDS * 4);

    cudaMemsetAsync(aggp, 0, (size_t)N_NODES * 64 * sizeof(unsigned int));
    cudaMemsetAsync(degp, 0, (size_t)N_NODES * sizeof(int));

    k_count  <<<(N_MSG + 255) / 256, 256>>>(ei);
    k_scan   <<<1, 1024>>>();
    k_scatter<<<(N_MSG + 255) / 256, 256>>>(ei);

    k_edge_csr<<<(N_MSG + 127) / 128, 256, ES_WORDS * 4>>>(x, pos, W1, b1, W2, b2);

    dim3 grd3((N_NODES + 127) / 128, 128 / 64);
    k_mlp_gemm<64, 128, true, true><<<grd3, 256>>>(aggp, W3, b3, (float*)g1, N_NODES);

    k_fused_mid<<<(N_NODES + 127) / 128, 256, FS_WORDS * 4>>>(
        (const float*)g1, W4, b4, W5, b5, Wf, bf, out, N_NODES);
}

// round 12
// speedup vs baseline: 1.8468x; 1.8468x over previous
#include <cuda_runtime.h>
#include <cuda_bf16.h>
#include <math.h>
#include <float.h>

#define N_NODES 50000
#define N_EDGES 1600000
#define N_MSG   (N_EDGES + N_NODES)
#define C_OUT   40

// ---------------- scratch (static device globals; no allocation) ----------------
__device__ __align__(256) unsigned int g_agg_u[N_NODES * 64]; // mapped-uint segment-max
__device__ __align__(256) float g_g1 [N_NODES * 128];

// ---------------- helpers ----------------
__device__ __forceinline__ unsigned int fmap(float v) {
    unsigned int k = __float_as_uint(v);
    return ((int)k < 0) ? ~k : (k | 0x80000000u);
}
__device__ __forceinline__ float funmap(unsigned int k) {
    return (k & 0x80000000u) ? __uint_as_float(k & 0x7FFFFFFFu)
                             : __uint_as_float(~k);
}
// tf32 mma reads only bits [31:13]; raw f32 bits == RZ-truncated tf32.
__device__ __forceinline__ void mma_tf32(float (&c)[4],
                                         unsigned int a0, unsigned int a1,
                                         unsigned int a2, unsigned int a3,
                                         unsigned int b0, unsigned int b1) {
    asm volatile(
        "mma.sync.aligned.m16n8k8.row.col.f32.tf32.tf32.f32 "
        "{%0,%1,%2,%3}, {%4,%5,%6,%7}, {%8,%9}, {%0,%1,%2,%3};"
        : "+f"(c[0]), "+f"(c[1]), "+f"(c[2]), "+f"(c[3])
        : "r"(a0), "r"(a1), "r"(a2), "r"(a3), "r"(b0), "r"(b1));
}

// ---------------- kernel 1: edge MLP v2 — fragment-direct layer1, no h1 smem ----------------
// 128 messages/block, 256 threads, 8 warps; warp w -> msgs [w*16, w*16+16), 64 channels.
// Thread (g,tg) computes h1 for msg0=mrow+g and msg1=mrow+g+8, channels k≡tg (mod 4),
// directly into mma A-fragment registers. W2 packed as uint2 pairs (k, k+4).
#define W2PS 68   // uint2 stride per (4ks+tg) row: 136 words ≡ 8 (mod 32) -> conflict-free LDS.64
__global__ __launch_bounds__(256) void k_edge_v2(
    const float* __restrict__ x,          // [N,3]
    const float* __restrict__ pos,        // [N,3]
    const int*   __restrict__ ei,         // [2,E] int32
    const float* __restrict__ W1,         // [6,64]
    const float* __restrict__ b1,         // [64]
    const float* __restrict__ W2,         // [64,64]
    const float* __restrict__ b2)         // [64]
{
    __shared__ float sW1[6 * 64];
    __shared__ float sb1[64];
    __shared__ float sb2[64];
    __shared__ uint2 sW2p[32 * W2PS];     // [4ks+tg][n], pair = (W2[8ks+tg][n], W2[8ks+tg+4][n])
    __shared__ float sIn[128 * 9];        // [msg][9], 6 used
    __shared__ int   sdst[128];

    const int tid  = threadIdx.x;
    const int lane = tid & 31;
    const int warp = tid >> 5;
    const int g    = lane >> 2;
    const int tg   = lane & 3;

    // stage weights
    for (int i = tid; i < 6 * 64; i += 256) sW1[i] = W1[i];
    if (tid < 64) { sb1[tid] = b1[tid]; sb2[tid] = b2[tid]; }
    for (int i = tid; i < 2048; i += 256) {
        int ks = i >> 8;             // 0..7
        int tt = (i >> 6) & 3;       // 0..3
        int n  = i & 63;
        float w0 = W2[(8 * ks + tt) * 64 + n];
        float w1 = W2[(8 * ks + tt + 4) * 64 + n];
        sW2p[(4 * ks + tt) * W2PS + n] = make_uint2(__float_as_uint(w0), __float_as_uint(w1));
    }

    // stage message inputs (threads 0..127 only; single gather per message)
    const int m0 = blockIdx.x * 128;
    if (tid < 128) {
        int m = m0 + tid;
        int src = 0, dst = -1;
        if (m < N_MSG) {
            if (m < N_EDGES) { src = ei[m]; dst = ei[N_EDGES + m]; }
            else             { src = dst = m - N_EDGES; }   // self-loop
        }
        sdst[tid] = dst;
        float* ip = sIn + tid * 9;
        if (dst >= 0) {
            ip[0] = x[src * 3 + 0];
            ip[1] = x[src * 3 + 1];
            ip[2] = x[src * 3 + 2];
            ip[3] = pos[src * 3 + 0] - pos[dst * 3 + 0];
            ip[4] = pos[src * 3 + 1] - pos[dst * 3 + 1];
            ip[5] = pos[src * 3 + 2] - pos[dst * 3 + 2];
        } else {
            #pragma unroll
            for (int i = 0; i < 6; i++) ip[i] = 0.0f;
        }
    }
    __syncthreads();

    const int mrow = warp * 16;
    const int msg0 = mrow + g;
    const int msg1 = msg0 + 8;

    float in0[6], in1[6];
    #pragma unroll
    for (int i = 0; i < 6; i++) { in0[i] = sIn[msg0 * 9 + i]; in1[i] = sIn[msg1 * 9 + i]; }
    const int d0 = sdst[msg0];
    const int d1 = sdst[msg1];

    float c[8][4];
    #pragma unroll
    for (int nt = 0; nt < 8; nt++)
        #pragma unroll
        for (int q = 0; q < 4; q++) c[nt][q] = 0.0f;

    // fused layer1 (fragment-direct) + layer2 mma
    #pragma unroll
    for (int ks = 0; ks < 8; ks++) {
        const int ka = 8 * ks + tg;
        const int kb = ka + 4;
        float ha0 = sb1[ka], ha1 = sb1[kb];   // msg0, channels ka / kb
        float hb0 = sb1[ka], hb1 = sb1[kb];   // msg1
        #pragma unroll
        for (int i = 0; i < 6; i++) {
            float wA = sW1[i * 64 + ka];
            float wB = sW1[i * 64 + kb];
            ha0 = fmaf(in0[i], wA, ha0);
            ha1 = fmaf(in0[i], wB, ha1);
            hb0 = fmaf(in1[i], wA, hb0);
            hb1 = fmaf(in1[i], wB, hb1);
        }
        unsigned int a0 = __float_as_uint(fmaxf(ha0, 0.0f));   // A[msg0][ka]
        unsigned int a2 = __float_as_uint(fmaxf(ha1, 0.0f));   // A[msg0][kb]
        unsigned int a1 = __float_as_uint(fmaxf(hb0, 0.0f));   // A[msg1][ka]
        unsigned int a3 = __float_as_uint(fmaxf(hb1, 0.0f));   // A[msg1][kb]
        const uint2* wrow = sW2p + (4 * ks + tg) * W2PS;
        #pragma unroll
        for (int nt = 0; nt < 8; nt++) {
            uint2 b = wrow[nt * 8 + g];
            mma_tf32(c[nt], a0, a1, a2, a3, b.x, b.y);
        }
    }

    // epilogue: +b2, RED.MAX.U32 scatter (validated mapping from R10)
    #pragma unroll
    for (int nt = 0; nt < 8; nt++) {
        int ch = nt * 8 + 2 * tg;
        float bv0 = sb2[ch], bv1 = sb2[ch + 1];
        if (d0 >= 0) {
            atomicMax(g_agg_u + (size_t)d0 * 64 + ch,     fmap(c[nt][0] + bv0));
            atomicMax(g_agg_u + (size_t)d0 * 64 + ch + 1, fmap(c[nt][1] + bv1));
        }
        if (d1 >= 0) {
            atomicMax(g_agg_u + (size_t)d1 * 64 + ch,     fmap(c[nt][2] + bv0));
            atomicMax(g_agg_u + (size_t)d1 * 64 + ch + 1, fmap(c[nt][3] + bv1));
        }
    }
}

// ---------------- proven fp32 register-tiled GEMM (64 -> 128 layer) ----------------
template<int K_TOT, int NOUT, bool RELU_OUT, bool UNMAP>
__global__ __launch_bounds__(256) void k_mlp_gemm(
    const void* __restrict__ Av,
    const float* __restrict__ W,
    const float* __restrict__ b,
    float* __restrict__ C,
    int nrows)
{
    __shared__ float As[32][129];
    __shared__ float Bs[32][64];

    const int tid = threadIdx.x;
    const int n0 = blockIdx.x * 128;
    const int o0 = blockIdx.y * 64;
    const int ot = tid & 15;
    const int nt = tid >> 4;

    const float* Af = (const float*)Av;
    const unsigned int* Au = (const unsigned int*)Av;

    float acc[8][4];
    #pragma unroll
    for (int j = 0; j < 8; j++)
        #pragma unroll
        for (int q = 0; q < 4; q++) acc[j][q] = 0.0f;

    const int kk = tid & 31;
    const int nr = tid >> 5;
    const int oo = tid & 63;
    const int kb = tid >> 6;

    for (int k0 = 0; k0 < K_TOT; k0 += 32) {
        #pragma unroll
        for (int jj = 0; jj < 16; jj++) {
            int n = nr * 16 + jj;
            int row = n0 + n;
            float v = 0.0f;
            if (row < nrows) {
                size_t idx = (size_t)row * K_TOT + k0 + kk;
                v = UNMAP ? funmap(Au[idx]) : Af[idx];
            }
            As[kk][n] = v;
        }
        #pragma unroll
        for (int jj = 0; jj < 8; jj++) {
            int k = kb * 8 + jj;
            Bs[k][oo] = W[(size_t)(k0 + k) * NOUT + o0 + oo];
        }
        __syncthreads();

        #pragma unroll
        for (int k = 0; k < 32; k++) {
            float4 wv = *(const float4*)&Bs[k][ot * 4];
            float av[8];
            #pragma unroll
            for (int j = 0; j < 8; j++) av[j] = As[k][nt * 8 + j];
            #pragma unroll
            for (int j = 0; j < 8; j++) {
                acc[j][0] = fmaf(av[j], wv.x, acc[j][0]);
                acc[j][1] = fmaf(av[j], wv.y, acc[j][1]);
                acc[j][2] = fmaf(av[j], wv.z, acc[j][2]);
                acc[j][3] = fmaf(av[j], wv.w, acc[j][3]);
            }
        }
        __syncthreads();
    }

    float bias0 = b[o0 + ot * 4 + 0];
    float bias1 = b[o0 + ot * 4 + 1];
    float bias2 = b[o0 + ot * 4 + 2];
    float bias3 = b[o0 + ot * 4 + 3];
    #pragma unroll
    for (int j = 0; j < 8; j++) {
        int row = n0 + nt * 8 + j;
        if (row >= nrows) continue;
        float4 v;
        v.x = acc[j][0] + bias0;
        v.y = acc[j][1] + bias1;
        v.z = acc[j][2] + bias2;
        v.w = acc[j][3] + bias3;
        if (RELU_OUT) {
            v.x = fmaxf(v.x, 0.0f); v.y = fmaxf(v.y, 0.0f);
            v.z = fmaxf(v.z, 0.0f); v.w = fmaxf(v.w, 0.0f);
        }
        *(float4*)&C[(size_t)row * NOUT + o0 + ot * 4] = v;
    }
}

// ---------------- fused: relu(g1@W4+b4)@W5+b5 -> relu -> fc -> log_softmax ----------------
#define FS_G1 0                     // [128m][132]
#define FS_B  16896                 // W4 chunk [128k][136] / W5 chunk [128k][72] / Wf [64*40]
#define FS_T  34304                 // [128m][132] relu tile / g3 tile [128m][68]
#define FS_B4 51200                 // [128] / bf [40]
#define FS_B5 51328                 // [64]
#define FS_WORDS 51392              // 205,568 bytes dynamic smem

__global__ __launch_bounds__(256) void k_fused_mid(
    const float* __restrict__ A,    // g1 [nrows,128]
    const float* __restrict__ W4,   // [128,1024]
    const float* __restrict__ b4,   // [1024]
    const float* __restrict__ W5,   // [1024,64]
    const float* __restrict__ b5,   // [64]
    const float* __restrict__ Wf,   // [64,40]
    const float* __restrict__ bf,   // [40]
    float* __restrict__ out,        // [nrows,40]
    int nrows)
{
    extern __shared__ unsigned int sm[];
    const int tid  = threadIdx.x;
    const int lane = tid & 31;
    const int warp = tid >> 5;
    const int wm   = warp >> 1;
    const int wn   = warp & 1;
    const int g    = lane >> 2;
    const int tg   = lane & 3;
    const int mrow = wm * 32;
    const int n0   = blockIdx.x * 128;

    #pragma unroll
    for (int i = 0; i < 16; i++) {
        int idx = tid + i * 256;
        int mm = idx >> 5, q = idx & 31;
        int row = n0 + mm;
        uint4 v = make_uint4(0u, 0u, 0u, 0u);
        if (row < nrows) v = *(const uint4*)&A[(size_t)row * 128 + q * 4];
        *(uint4*)&sm[FS_G1 + mm * 132 + q * 4] = v;
    }
    if (tid < 64) sm[FS_B5 + tid] = __float_as_uint(b5[tid]);

    float acc2[2][4][4];
    #pragma unroll
    for (int mt = 0; mt < 2; mt++)
        #pragma unroll
        for (int nt = 0; nt < 4; nt++)
            #pragma unroll
            for (int q = 0; q < 4; q++) acc2[mt][nt][q] = 0.0f;

    for (int cch = 0; cch < 8; cch++) {
        __syncthreads();
        #pragma unroll
        for (int i = 0; i < 16; i++) {
            int idx = tid + i * 256;
            int k = idx >> 5, q = idx & 31;
            *(uint4*)&sm[FS_B + k * 136 + q * 4] =
                *(const uint4*)&W4[(size_t)k * 1024 + cch * 128 + q * 4];
        }
        if (tid < 128) sm[FS_B4 + tid] = __float_as_uint(b4[cch * 128 + tid]);
        __syncthreads();

        float acc1[2][8][4];
        #pragma unroll
        for (int mt = 0; mt < 2; mt++)
            #pragma unroll
            for (int nt = 0; nt < 8; nt++)
                #pragma unroll
                for (int q = 0; q < 4; q++) acc1[mt][nt][q] = 0.0f;

        #pragma unroll
        for (int ks = 0; ks < 16; ks++) {
            const int k0 = ks * 8;
            unsigned int a[2][4];
            #pragma unroll
            for (int mt = 0; mt < 2; mt++) {
                int mr = mrow + mt * 16;
                a[mt][0] = sm[FS_G1 + (mr + g    ) * 132 + k0 + tg    ];
                a[mt][1] = sm[FS_G1 + (mr + g + 8) * 132 + k0 + tg    ];
                a[mt][2] = sm[FS_G1 + (mr + g    ) * 132 + k0 + tg + 4];
                a[mt][3] = sm[FS_G1 + (mr + g + 8) * 132 + k0 + tg + 4];
            }
            #pragma unroll
            for (int nt = 0; nt < 8; nt++) {
                int nc = wn * 64 + nt * 8 + g;
                unsigned int b0 = sm[FS_B + (k0 + tg    ) * 136 + nc];
                unsigned int b1 = sm[FS_B + (k0 + tg + 4) * 136 + nc];
                #pragma unroll
                for (int mt = 0; mt < 2; mt++)
                    mma_tf32(acc1[mt][nt], a[mt][0], a[mt][1], a[mt][2], a[mt][3], b0, b1);
            }
        }
        __syncthreads();

        #pragma unroll
        for (int nt = 0; nt < 8; nt++) {
            int col = wn * 64 + nt * 8 + 2 * tg;
            float bv0 = __uint_as_float(sm[FS_B4 + col]);
            float bv1 = __uint_as_float(sm[FS_B4 + col + 1]);
            #pragma unroll
            for (int mt = 0; mt < 2; mt++) {
                int r0 = mrow + mt * 16 + g;
                int r1 = r0 + 8;
                sm[FS_T + r0 * 132 + col    ] = __float_as_uint(fmaxf(acc1[mt][nt][0] + bv0, 0.0f));
                sm[FS_T + r0 * 132 + col + 1] = __float_as_uint(fmaxf(acc1[mt][nt][1] + bv1, 0.0f));
                sm[FS_T + r1 * 132 + col    ] = __float_as_uint(fmaxf(acc1[mt][nt][2] + bv0, 0.0f));
                sm[FS_T + r1 * 132 + col + 1] = __float_as_uint(fmaxf(acc1[mt][nt][3] + bv1, 0.0f));
            }
        }
        #pragma unroll
        for (int i = 0; i < 8; i++) {
            int idx = tid + i * 256;
            int k = idx >> 4, q = idx & 15;
            *(uint4*)&sm[FS_B + k * 72 + q * 4] =
                *(const uint4*)&W5[(size_t)(cch * 128 + k) * 64 + q * 4];
        }
        __syncthreads();

        #pragma unroll
        for (int ks = 0; ks < 16; ks++) {
            const int k0 = ks * 8;
            unsigned int a[2][4];
            #pragma unroll
            for (int mt = 0; mt < 2; mt++) {
                int mr = mrow + mt * 16;
                a[mt][0] = sm[FS_T + (mr + g    ) * 132 + k0 + tg    ];
                a[mt][1] = sm[FS_T + (mr + g + 8) * 132 + k0 + tg    ];
                a[mt][2] = sm[FS_T + (mr + g    ) * 132 + k0 + tg + 4];
                a[mt][3] = sm[FS_T + (mr + g + 8) * 132 + k0 + tg + 4];
            }
            #pragma unroll
            for (int nt = 0; nt < 4; nt++) {
                int nc = wn * 32 + nt * 8 + g;
                unsigned int b0 = sm[FS_B + (k0 + tg    ) * 72 + nc];
                unsigned int b1 = sm[FS_B + (k0 + tg + 4) * 72 + nc];
                #pragma unroll
                for (int mt = 0; mt < 2; mt++)
                    mma_tf32(acc2[mt][nt], a[mt][0], a[mt][1], a[mt][2], a[mt][3], b0, b1);
            }
        }
    }
    __syncthreads();

    for (int i = tid; i < 64 * 40; i += 256) sm[FS_B + i] = __float_as_uint(Wf[i]);
    if (tid < 40) sm[FS_B4 + tid] = __float_as_uint(bf[tid]);
    #pragma unroll
    for (int nt = 0; nt < 4; nt++) {
        int col = wn * 32 + nt * 8 + 2 * tg;
        float bv0 = __uint_as_float(sm[FS_B5 + col]);
        float bv1 = __uint_as_float(sm[FS_B5 + col + 1]);
        #pragma unroll
        for (int mt = 0; mt < 2; mt++) {
            int r0 = mrow + mt * 16 + g;
            int r1 = r0 + 8;
            sm[FS_T + r0 * 68 + col    ] = __float_as_uint(acc2[mt][nt][0] + bv0);
            sm[FS_T + r0 * 68 + col + 1] = __float_as_uint(acc2[mt][nt][1] + bv1);
            sm[FS_T + r1 * 68 + col    ] = __float_as_uint(acc2[mt][nt][2] + bv0);
            sm[FS_T + r1 * 68 + col + 1] = __float_as_uint(acc2[mt][nt][3] + bv1);
        }
    }
    __syncthreads();

    for (int j = 0; j < 16; j++) {
        int nl = warp * 16 + j;
        int node = n0 + nl;
        if (node >= nrows) break;
        float v0 = __uint_as_float(sm[FS_B4 + lane]);
        float v1 = (lane < 8) ? __uint_as_float(sm[FS_B4 + lane + 32]) : -FLT_MAX;
        #pragma unroll
        for (int k = 0; k < 64; k++) {
            float a = fmaxf(__uint_as_float(sm[FS_T + nl * 68 + k]), 0.0f);
            float w0 = __uint_as_float(sm[FS_B + k * 40 + lane]);
            v0 = fmaf(a, w0, v0);
            if (lane < 8) {
                float w1 = __uint_as_float(sm[FS_B + k * 40 + lane + 32]);
                v1 = fmaf(a, w1, v1);
            }
        }
        float mx = fmaxf(v0, v1);
        #pragma unroll
        for (int off = 16; off > 0; off >>= 1)
            mx = fmaxf(mx, __shfl_xor_sync(0xFFFFFFFFu, mx, off));
        float s = __expf(v0 - mx) + ((lane < 8) ? __expf(v1 - mx) : 0.0f);
        #pragma unroll
        for (int off = 16; off > 0; off >>= 1)
            s += __shfl_xor_sync(0xFFFFFFFFu, s, off);
        float ls = __logf(s);
        float* op = out + (size_t)node * C_OUT;
        op[lane] = v0 - mx - ls;
        if (lane < 8) op[lane + 32] = v1 - mx - ls;
    }
}

// ---------------- launcher ----------------
extern "C" void kernel_launch(void* const* d_in, const int* in_sizes, int n_in,
                              void* d_out, int out_size) {
    const float* x   = (const float*)d_in[0];
    const float* pos = (const float*)d_in[1];
    const int*   ei  = (const int*)d_in[2];
    const float* W1 = (const float*)d_in[3];
    const float* b1 = (const float*)d_in[4];
    const float* W2 = (const float*)d_in[5];
    const float* b2 = (const float*)d_in[6];
    const float* W3 = (const float*)d_in[7];
    const float* b3 = (const float*)d_in[8];
    const float* W4 = (const float*)d_in[9];
    const float* b4 = (const float*)d_in[10];
    const float* W5 = (const float*)d_in[11];
    const float* b5 = (const float*)d_in[12];
    const float* Wf = (const float*)d_in[13];
    const float* bf = (const float*)d_in[14];
    float* out = (float*)d_out;

    void* aggp = nullptr; void* g1 = nullptr;
    cudaGetSymbolAddress(&aggp, g_agg_u);
    cudaGetSymbolAddress(&g1, g_g1);

    cudaFuncSetAttribute(k_fused_mid, cudaFuncAttributeMaxDynamicSharedMemorySize,
                         FS_WORDS * 4);

    // mapped-uint 0 is below every mapped float -> -inf init
    cudaMemsetAsync(aggp, 0, (size_t)N_NODES * 64 * sizeof(unsigned int));

    k_edge_v2<<<(N_MSG + 127) / 128, 256>>>(x, pos, ei, W1, b1, W2, b2);

    dim3 grd3((N_NODES + 127) / 128, 128 / 64);
    k_mlp_gemm<64, 128, true, true><<<grd3, 256>>>(aggp, W3, b3, (float*)g1, N_NODES);

    k_fused_mid<<<(N_NODES + 127) / 128, 256, FS_WORDS * 4>>>(
        (const float*)g1, W4, b4, W5, b5, Wf, bf, out, N_NODES);
}

// round 13
// speedup vs baseline: 1.9077x; 1.0330x over previous
#include <cuda_runtime.h>
#include <cuda_bf16.h>
#include <math.h>
#include <float.h>

#define N_NODES 50000
#define N_EDGES 1600000
#define N_MSG   (N_EDGES + N_NODES)
#define C_OUT   40

// ---------------- scratch (static device globals; no allocation) ----------------
__device__ __align__(256) unsigned int g_agg_u[N_NODES * 64]; // mapped-uint segment-max
__device__ __align__(256) float g_g1 [N_NODES * 128];

// ---------------- helpers ----------------
__device__ __forceinline__ unsigned int fmap(float v) {
    unsigned int k = __float_as_uint(v);
    return ((int)k < 0) ? ~k : (k | 0x80000000u);
}
__device__ __forceinline__ float funmap(unsigned int k) {
    return (k & 0x80000000u) ? __uint_as_float(k & 0x7FFFFFFFu)
                             : __uint_as_float(~k);
}
// tf32 mma reads only bits [31:13]; raw f32 bits == RZ-truncated tf32.
__device__ __forceinline__ void mma_tf32(float (&c)[4],
                                         unsigned int a0, unsigned int a1,
                                         unsigned int a2, unsigned int a3,
                                         unsigned int b0, unsigned int b1) {
    asm volatile(
        "mma.sync.aligned.m16n8k8.row.col.f32.tf32.tf32.f32 "
        "{%0,%1,%2,%3}, {%4,%5,%6,%7}, {%8,%9}, {%0,%1,%2,%3};"
        : "+f"(c[0]), "+f"(c[1]), "+f"(c[2]), "+f"(c[3])
        : "r"(a0), "r"(a1), "r"(a2), "r"(a3), "r"(b0), "r"(b1));
}

// ---------------- kernel 1: edge MLP v3 — 32 msgs/warp, B-fragments amortized 2x ----------------
// 256 messages/block, 256 threads, 8 warps; warp w -> msgs [w*32, w*32+32).
// Thread (g,tg) computes h1 for 4 msgs (mrow+g, +8, +16, +24), channels k≡tg (mod 4),
// directly into mma A-fragments. Each W2 uint2 LDS.64 feeds TWO mmas (mt=0/1).
#define W2PS 68   // uint2 stride: 136 words ≡ 8 (mod 32) -> conflict-free LDS.64
__global__ __launch_bounds__(256) void k_edge_v3(
    const float* __restrict__ x,          // [N,3]
    const float* __restrict__ pos,        // [N,3]
    const int*   __restrict__ ei,         // [2,E] int32
    const float* __restrict__ W1,         // [6,64]
    const float* __restrict__ b1,         // [64]
    const float* __restrict__ W2,         // [64,64]
    const float* __restrict__ b2)         // [64]
{
    __shared__ float sW1[6 * 64];
    __shared__ float sb1[64];
    __shared__ float sb2[64];
    __shared__ uint2 sW2p[32 * W2PS];     // [4ks+tg][n], pair = (W2[8ks+tg][n], W2[8ks+tg+4][n])
    __shared__ float sIn[256 * 9];        // [msg][9], 6 used
    __shared__ int   sdst[256];

    const int tid  = threadIdx.x;
    const int lane = tid & 31;
    const int warp = tid >> 5;
    const int g    = lane >> 2;
    const int tg   = lane & 3;

    // stage weights
    for (int i = tid; i < 6 * 64; i += 256) sW1[i] = W1[i];
    if (tid < 64) { sb1[tid] = b1[tid]; sb2[tid] = b2[tid]; }
    for (int i = tid; i < 2048; i += 256) {
        int ks = i >> 8;             // 0..7
        int tt = (i >> 6) & 3;       // 0..3
        int n  = i & 63;
        float w0 = W2[(8 * ks + tt) * 64 + n];
        float w1 = W2[(8 * ks + tt + 4) * 64 + n];
        sW2p[(4 * ks + tt) * W2PS + n] = make_uint2(__float_as_uint(w0), __float_as_uint(w1));
    }

    // stage message inputs: one message per thread
    const int m0 = blockIdx.x * 256;
    {
        int m = m0 + tid;
        int src = 0, dst = -1;
        if (m < N_MSG) {
            if (m < N_EDGES) { src = ei[m]; dst = ei[N_EDGES + m]; }
            else             { src = dst = m - N_EDGES; }   // self-loop
        }
        sdst[tid] = dst;
        float* ip = sIn + tid * 9;
        if (dst >= 0) {
            ip[0] = x[src * 3 + 0];
            ip[1] = x[src * 3 + 1];
            ip[2] = x[src * 3 + 2];
            ip[3] = pos[src * 3 + 0] - pos[dst * 3 + 0];
            ip[4] = pos[src * 3 + 1] - pos[dst * 3 + 1];
            ip[5] = pos[src * 3 + 2] - pos[dst * 3 + 2];
        } else {
            #pragma unroll
            for (int i = 0; i < 6; i++) ip[i] = 0.0f;
        }
    }
    __syncthreads();

    const int mrow = warp * 32;
    int mr[4];
    mr[0] = mrow + g; mr[1] = mr[0] + 8; mr[2] = mr[0] + 16; mr[3] = mr[0] + 24;

    float in[4][6];
    int d[4];
    #pragma unroll
    for (int r = 0; r < 4; r++) {
        d[r] = sdst[mr[r]];
        #pragma unroll
        for (int i = 0; i < 6; i++) in[r][i] = sIn[mr[r] * 9 + i];
    }

    float c[2][8][4];
    #pragma unroll
    for (int mt = 0; mt < 2; mt++)
        #pragma unroll
        for (int nt = 0; nt < 8; nt++)
            #pragma unroll
            for (int q = 0; q < 4; q++) c[mt][nt][q] = 0.0f;

    // fused layer1 (fragment-direct, 4 msgs) + layer2 mma (B amortized over 2 m-tiles)
    #pragma unroll
    for (int ks = 0; ks < 8; ks++) {
        const int ka = 8 * ks + tg;
        const int kb = ka + 4;
        const float bka = sb1[ka], bkb = sb1[kb];
        float hA[4], hB[4];
        #pragma unroll
        for (int r = 0; r < 4; r++) { hA[r] = bka; hB[r] = bkb; }
        #pragma unroll
        for (int i = 0; i < 6; i++) {
            float wA = sW1[i * 64 + ka];
            float wB = sW1[i * 64 + kb];
            #pragma unroll
            for (int r = 0; r < 4; r++) {
                hA[r] = fmaf(in[r][i], wA, hA[r]);
                hB[r] = fmaf(in[r][i], wB, hB[r]);
            }
        }
        unsigned int af[2][4];
        #pragma unroll
        for (int mt = 0; mt < 2; mt++) {
            af[mt][0] = __float_as_uint(fmaxf(hA[2 * mt    ], 0.0f));  // A[row g   ][ka]
            af[mt][1] = __float_as_uint(fmaxf(hA[2 * mt + 1], 0.0f));  // A[row g+8 ][ka]
            af[mt][2] = __float_as_uint(fmaxf(hB[2 * mt    ], 0.0f));  // A[row g   ][kb]
            af[mt][3] = __float_as_uint(fmaxf(hB[2 * mt + 1], 0.0f));  // A[row g+8 ][kb]
        }
        const uint2* wrow = sW2p + (4 * ks + tg) * W2PS;
        #pragma unroll
        for (int nt = 0; nt < 8; nt++) {
            uint2 b = wrow[nt * 8 + g];
            mma_tf32(c[0][nt], af[0][0], af[0][1], af[0][2], af[0][3], b.x, b.y);
            mma_tf32(c[1][nt], af[1][0], af[1][1], af[1][2], af[1][3], b.x, b.y);
        }
    }

    // epilogue: +b2, RED.MAX.U32 scatter (validated mapping)
    #pragma unroll
    for (int mt = 0; mt < 2; mt++) {
        const int d0 = d[2 * mt];
        const int d1 = d[2 * mt + 1];
        #pragma unroll
        for (int nt = 0; nt < 8; nt++) {
            int ch = nt * 8 + 2 * tg;
            float bv0 = sb2[ch], bv1 = sb2[ch + 1];
            if (d0 >= 0) {
                atomicMax(g_agg_u + (size_t)d0 * 64 + ch,     fmap(c[mt][nt][0] + bv0));
                atomicMax(g_agg_u + (size_t)d0 * 64 + ch + 1, fmap(c[mt][nt][1] + bv1));
            }
            if (d1 >= 0) {
                atomicMax(g_agg_u + (size_t)d1 * 64 + ch,     fmap(c[mt][nt][2] + bv0));
                atomicMax(g_agg_u + (size_t)d1 * 64 + ch + 1, fmap(c[mt][nt][3] + bv1));
            }
        }
    }
}

// ---------------- proven fp32 register-tiled GEMM (64 -> 128 layer) ----------------
template<int K_TOT, int NOUT, bool RELU_OUT, bool UNMAP>
__global__ __launch_bounds__(256) void k_mlp_gemm(
    const void* __restrict__ Av,
    const float* __restrict__ W,
    const float* __restrict__ b,
    float* __restrict__ C,
    int nrows)
{
    __shared__ float As[32][129];
    __shared__ float Bs[32][64];

    const int tid = threadIdx.x;
    const int n0 = blockIdx.x * 128;
    const int o0 = blockIdx.y * 64;
    const int ot = tid & 15;
    const int nt = tid >> 4;

    const float* Af = (const float*)Av;
    const unsigned int* Au = (const unsigned int*)Av;

    float acc[8][4];
    #pragma unroll
    for (int j = 0; j < 8; j++)
        #pragma unroll
        for (int q = 0; q < 4; q++) acc[j][q] = 0.0f;

    const int kk = tid & 31;
    const int nr = tid >> 5;
    const int oo = tid & 63;
    const int kb = tid >> 6;

    for (int k0 = 0; k0 < K_TOT; k0 += 32) {
        #pragma unroll
        for (int jj = 0; jj < 16; jj++) {
            int n = nr * 16 + jj;
            int row = n0 + n;
            float v = 0.0f;
            if (row < nrows) {
                size_t idx = (size_t)row * K_TOT + k0 + kk;
                v = UNMAP ? funmap(Au[idx]) : Af[idx];
            }
            As[kk][n] = v;
        }
        #pragma unroll
        for (int jj = 0; jj < 8; jj++) {
            int k = kb * 8 + jj;
            Bs[k][oo] = W[(size_t)(k0 + k) * NOUT + o0 + oo];
        }
        __syncthreads();

        #pragma unroll
        for (int k = 0; k < 32; k++) {
            float4 wv = *(const float4*)&Bs[k][ot * 4];
            float av[8];
            #pragma unroll
            for (int j = 0; j < 8; j++) av[j] = As[k][nt * 8 + j];
            #pragma unroll
            for (int j = 0; j < 8; j++) {
                acc[j][0] = fmaf(av[j], wv.x, acc[j][0]);
                acc[j][1] = fmaf(av[j], wv.y, acc[j][1]);
                acc[j][2] = fmaf(av[j], wv.z, acc[j][2]);
                acc[j][3] = fmaf(av[j], wv.w, acc[j][3]);
            }
        }
        __syncthreads();
    }

    float bias0 = b[o0 + ot * 4 + 0];
    float bias1 = b[o0 + ot * 4 + 1];
    float bias2 = b[o0 + ot * 4 + 2];
    float bias3 = b[o0 + ot * 4 + 3];
    #pragma unroll
    for (int j = 0; j < 8; j++) {
        int row = n0 + nt * 8 + j;
        if (row >= nrows) continue;
        float4 v;
        v.x = acc[j][0] + bias0;
        v.y = acc[j][1] + bias1;
        v.z = acc[j][2] + bias2;
        v.w = acc[j][3] + bias3;
        if (RELU_OUT) {
            v.x = fmaxf(v.x, 0.0f); v.y = fmaxf(v.y, 0.0f);
            v.z = fmaxf(v.z, 0.0f); v.w = fmaxf(v.w, 0.0f);
        }
        *(float4*)&C[(size_t)row * NOUT + o0 + ot * 4] = v;
    }
}

// ---------------- fused: relu(g1@W4+b4)@W5+b5 -> relu -> fc -> log_softmax ----------------
#define FS_G1 0                     // [128m][132]
#define FS_B  16896                 // W4 chunk [128k][136] / W5 chunk [128k][72] / Wf [64*40]
#define FS_T  34304                 // [128m][132] relu tile / g3 tile [128m][68]
#define FS_B4 51200                 // [128] / bf [40]
#define FS_B5 51328                 // [64]
#define FS_WORDS 51392              // 205,568 bytes dynamic smem

__global__ __launch_bounds__(256) void k_fused_mid(
    const float* __restrict__ A,    // g1 [nrows,128]
    const float* __restrict__ W4,   // [128,1024]
    const float* __restrict__ b4,   // [1024]
    const float* __restrict__ W5,   // [1024,64]
    const float* __restrict__ b5,   // [64]
    const float* __restrict__ Wf,   // [64,40]
    const float* __restrict__ bf,   // [40]
    float* __restrict__ out,        // [nrows,40]
    int nrows)
{
    extern __shared__ unsigned int sm[];
    const int tid  = threadIdx.x;
    const int lane = tid & 31;
    const int warp = tid >> 5;
    const int wm   = warp >> 1;
    const int wn   = warp & 1;
    const int g    = lane >> 2;
    const int tg   = lane & 3;
    const int mrow = wm * 32;
    const int n0   = blockIdx.x * 128;

    #pragma unroll
    for (int i = 0; i < 16; i++) {
        int idx = tid + i * 256;
        int mm = idx >> 5, q = idx & 31;
        int row = n0 + mm;
        uint4 v = make_uint4(0u, 0u, 0u, 0u);
        if (row < nrows) v = *(const uint4*)&A[(size_t)row * 128 + q * 4];
        *(uint4*)&sm[FS_G1 + mm * 132 + q * 4] = v;
    }
    if (tid < 64) sm[FS_B5 + tid] = __float_as_uint(b5[tid]);

    float acc2[2][4][4];
    #pragma unroll
    for (int mt = 0; mt < 2; mt++)
        #pragma unroll
        for (int nt = 0; nt < 4; nt++)
            #pragma unroll
            for (int q = 0; q < 4; q++) acc2[mt][nt][q] = 0.0f;

    for (int cch = 0; cch < 8; cch++) {
        __syncthreads();
        #pragma unroll
        for (int i = 0; i < 16; i++) {
            int idx = tid + i * 256;
            int k = idx >> 5, q = idx & 31;
            *(uint4*)&sm[FS_B + k * 136 + q * 4] =
                *(const uint4*)&W4[(size_t)k * 1024 + cch * 128 + q * 4];
        }
        if (tid < 128) sm[FS_B4 + tid] = __float_as_uint(b4[cch * 128 + tid]);
        __syncthreads();

        float acc1[2][8][4];
        #pragma unroll
        for (int mt = 0; mt < 2; mt++)
            #pragma unroll
            for (int nt = 0; nt < 8; nt++)
                #pragma unroll
                for (int q = 0; q < 4; q++) acc1[mt][nt][q] = 0.0f;

        #pragma unroll
        for (int ks = 0; ks < 16; ks++) {
            const int k0 = ks * 8;
            unsigned int a[2][4];
            #pragma unroll
            for (int mt = 0; mt < 2; mt++) {
                int mr = mrow + mt * 16;
                a[mt][0] = sm[FS_G1 + (mr + g    ) * 132 + k0 + tg    ];
                a[mt][1] = sm[FS_G1 + (mr + g + 8) * 132 + k0 + tg    ];
                a[mt][2] = sm[FS_G1 + (mr + g    ) * 132 + k0 + tg + 4];
                a[mt][3] = sm[FS_G1 + (mr + g + 8) * 132 + k0 + tg + 4];
            }
            #pragma unroll
            for (int nt = 0; nt < 8; nt++) {
                int nc = wn * 64 + nt * 8 + g;
                unsigned int b0 = sm[FS_B + (k0 + tg    ) * 136 + nc];
                unsigned int b1 = sm[FS_B + (k0 + tg + 4) * 136 + nc];
                #pragma unroll
                for (int mt = 0; mt < 2; mt++)
                    mma_tf32(acc1[mt][nt], a[mt][0], a[mt][1], a[mt][2], a[mt][3], b0, b1);
            }
        }
        __syncthreads();

        #pragma unroll
        for (int nt = 0; nt < 8; nt++) {
            int col = wn * 64 + nt * 8 + 2 * tg;
            float bv0 = __uint_as_float(sm[FS_B4 + col]);
            float bv1 = __uint_as_float(sm[FS_B4 + col + 1]);
            #pragma unroll
            for (int mt = 0; mt < 2; mt++) {
                int r0 = mrow + mt * 16 + g;
                int r1 = r0 + 8;
                sm[FS_T + r0 * 132 + col    ] = __float_as_uint(fmaxf(acc1[mt][nt][0] + bv0, 0.0f));
                sm[FS_T + r0 * 132 + col + 1] = __float_as_uint(fmaxf(acc1[mt][nt][1] + bv1, 0.0f));
                sm[FS_T + r1 * 132 + col    ] = __float_as_uint(fmaxf(acc1[mt][nt][2] + bv0, 0.0f));
                sm[FS_T + r1 * 132 + col + 1] = __float_as_uint(fmaxf(acc1[mt][nt][3] + bv1, 0.0f));
            }
        }
        #pragma unroll
        for (int i = 0; i < 8; i++) {
            int idx = tid + i * 256;
            int k = idx >> 4, q = idx & 15;
            *(uint4*)&sm[FS_B + k * 72 + q * 4] =
                *(const uint4*)&W5[(size_t)(cch * 128 + k) * 64 + q * 4];
        }
        __syncthreads();

        #pragma unroll
        for (int ks = 0; ks < 16; ks++) {
            const int k0 = ks * 8;
            unsigned int a[2][4];
            #pragma unroll
            for (int mt = 0; mt < 2; mt++) {
                int mr = mrow + mt * 16;
                a[mt][0] = sm[FS_T + (mr + g    ) * 132 + k0 + tg    ];
                a[mt][1] = sm[FS_T + (mr + g + 8) * 132 + k0 + tg    ];
                a[mt][2] = sm[FS_T + (mr + g    ) * 132 + k0 + tg + 4];
                a[mt][3] = sm[FS_T + (mr + g + 8) * 132 + k0 + tg + 4];
            }
            #pragma unroll
            for (int nt = 0; nt < 4; nt++) {
                int nc = wn * 32 + nt * 8 + g;
                unsigned int b0 = sm[FS_B + (k0 + tg    ) * 72 + nc];
                unsigned int b1 = sm[FS_B + (k0 + tg + 4) * 72 + nc];
                #pragma unroll
                for (int mt = 0; mt < 2; mt++)
                    mma_tf32(acc2[mt][nt], a[mt][0], a[mt][1], a[mt][2], a[mt][3], b0, b1);
            }
        }
    }
    __syncthreads();

    for (int i = tid; i < 64 * 40; i += 256) sm[FS_B + i] = __float_as_uint(Wf[i]);
    if (tid < 40) sm[FS_B4 + tid] = __float_as_uint(bf[tid]);
    #pragma unroll
    for (int nt = 0; nt < 4; nt++) {
        int col = wn * 32 + nt * 8 + 2 * tg;
        float bv0 = __uint_as_float(sm[FS_B5 + col]);
        float bv1 = __uint_as_float(sm[FS_B5 + col + 1]);
        #pragma unroll
        for (int mt = 0; mt < 2; mt++) {
            int r0 = mrow + mt * 16 + g;
            int r1 = r0 + 8;
            sm[FS_T + r0 * 68 + col    ] = __float_as_uint(acc2[mt][nt][0] + bv0);
            sm[FS_T + r0 * 68 + col + 1] = __float_as_uint(acc2[mt][nt][1] + bv1);
            sm[FS_T + r1 * 68 + col    ] = __float_as_uint(acc2[mt][nt][2] + bv0);
            sm[FS_T + r1 * 68 + col + 1] = __float_as_uint(acc2[mt][nt][3] + bv1);
        }
    }
    __syncthreads();

    for (int j = 0; j < 16; j++) {
        int nl = warp * 16 + j;
        int node = n0 + nl;
        if (node >= nrows) break;
        float v0 = __uint_as_float(sm[FS_B4 + lane]);
        float v1 = (lane < 8) ? __uint_as_float(sm[FS_B4 + lane + 32]) : -FLT_MAX;
        #pragma unroll
        for (int k = 0; k < 64; k++) {
            float a = fmaxf(__uint_as_float(sm[FS_T + nl * 68 + k]), 0.0f);
            float w0 = __uint_as_float(sm[FS_B + k * 40 + lane]);
            v0 = fmaf(a, w0, v0);
            if (lane < 8) {
                float w1 = __uint_as_float(sm[FS_B + k * 40 + lane + 32]);
                v1 = fmaf(a, w1, v1);
            }
        }
        float mx = fmaxf(v0, v1);
        #pragma unroll
        for (int off = 16; off > 0; off >>= 1)
            mx = fmaxf(mx, __shfl_xor_sync(0xFFFFFFFFu, mx, off));
        float s = __expf(v0 - mx) + ((lane < 8) ? __expf(v1 - mx) : 0.0f);
        #pragma unroll
        for (int off = 16; off > 0; off >>= 1)
            s += __shfl_xor_sync(0xFFFFFFFFu, s, off);
        float ls = __logf(s);
        float* op = out + (size_t)node * C_OUT;
        op[lane] = v0 - mx - ls;
        if (lane < 8) op[lane + 32] = v1 - mx - ls;
    }
}

// ---------------- launcher ----------------
extern "C" void kernel_launch(void* const* d_in, const int* in_sizes, int n_in,
                              void* d_out, int out_size) {
    const float* x   = (const float*)d_in[0];
    const float* pos = (const float*)d_in[1];
    const int*   ei  = (const int*)d_in[2];
    const float* W1 = (const float*)d_in[3];
    const float* b1 = (const float*)d_in[4];
    const float* W2 = (const float*)d_in[5];
    const float* b2 = (const float*)d_in[6];
    const float* W3 = (const float*)d_in[7];
    const float* b3 = (const float*)d_in[8];
    const float* W4 = (const float*)d_in[9];
    const float* b4 = (const float*)d_in[10];
    const float* W5 = (const float*)d_in[11];
    const float* b5 = (const float*)d_in[12];
    const float* Wf = (const float*)d_in[13];
    const float* bf = (const float*)d_in[14];
    float* out = (float*)d_out;

    void* aggp = nullptr; void* g1 = nullptr;
    cudaGetSymbolAddress(&aggp, g_agg_u);
    cudaGetSymbolAddress(&g1, g_g1);

    cudaFuncSetAttribute(k_fused_mid, cudaFuncAttributeMaxDynamicSharedMemorySize,
                         FS_WORDS * 4);

    // mapped-uint 0 is below every mapped float -> -inf init
    cudaMemsetAsync(aggp, 0, (size_t)N_NODES * 64 * sizeof(unsigned int));

    k_edge_v3<<<(N_MSG + 255) / 256, 256>>>(x, pos, ei, W1, b1, W2, b2);

    dim3 grd3((N_NODES + 127) / 128, 128 / 64);
    k_mlp_gemm<64, 128, true, true><<<grd3, 256>>>(aggp, W3, b3, (float*)g1, N_NODES);

    k_fused_mid<<<(N_NODES + 127) / 128, 256, FS_WORDS * 4>>>(
        (const float*)g1, W4, b4, W5, b5, Wf, bf, out, N_NODES);
}

// round 14
// speedup vs baseline: 1.9408x; 1.0173x over previous
#include <cuda_runtime.h>
#include <cuda_bf16.h>
#include <math.h>
#include <float.h>

#define N_NODES 50000
#define N_EDGES 1600000
#define N_MSG   (N_EDGES + N_NODES)
#define C_OUT   40

// ---------------- scratch (static device globals; no allocation) ----------------
__device__ __align__(256) unsigned int g_agg_u[N_NODES * 64]; // mapped-uint segment-max

// ---------------- helpers ----------------
__device__ __forceinline__ unsigned int fmap(float v) {
    unsigned int k = __float_as_uint(v);
    return ((int)k < 0) ? ~k : (k | 0x80000000u);
}
__device__ __forceinline__ float funmap(unsigned int k) {
    return (k & 0x80000000u) ? __uint_as_float(k & 0x7FFFFFFFu)
                             : __uint_as_float(~k);
}
// tf32 mma reads only bits [31:13]; raw f32 bits == RZ-truncated tf32.
__device__ __forceinline__ void mma_tf32(float (&c)[4],
                                         unsigned int a0, unsigned int a1,
                                         unsigned int a2, unsigned int a3,
                                         unsigned int b0, unsigned int b1) {
    asm volatile(
        "mma.sync.aligned.m16n8k8.row.col.f32.tf32.tf32.f32 "
        "{%0,%1,%2,%3}, {%4,%5,%6,%7}, {%8,%9}, {%0,%1,%2,%3};"
        : "+f"(c[0]), "+f"(c[1]), "+f"(c[2]), "+f"(c[3])
        : "r"(a0), "r"(a1), "r"(a2), "r"(a3), "r"(b0), "r"(b1));
}

// ---------------- kernel 1: edge MLP v4 — v3 tiling, two channel passes for occupancy ----------------
// 256 messages/block, 8 warps; warp w -> msgs [w*32, w*32+32).
// Pass p accumulates channels [p*32, p*32+32); layer-1 fragments recomputed per pass (cheap).
#define W2PS 68   // uint2 stride: 136 words ≡ 8 (mod 32) -> conflict-free LDS.64
__global__ __launch_bounds__(256, 3) void k_edge_v4(
    const float* __restrict__ x,          // [N,3]
    const float* __restrict__ pos,        // [N,3]
    const int*   __restrict__ ei,         // [2,E] int32
    const float* __restrict__ W1,         // [6,64]
    const float* __restrict__ b1,         // [64]
    const float* __restrict__ W2,         // [64,64]
    const float* __restrict__ b2)         // [64]
{
    __shared__ float sW1[6 * 64];
    __shared__ float sb1[64];
    __shared__ float sb2[64];
    __shared__ uint2 sW2p[32 * W2PS];     // [4ks+tg][n], pair = (W2[8ks+tg][n], W2[8ks+tg+4][n])
    __shared__ float sIn[256 * 9];        // [msg][9], 6 used
    __shared__ int   sdst[256];

    const int tid  = threadIdx.x;
    const int lane = tid & 31;
    const int warp = tid >> 5;
    const int g    = lane >> 2;
    const int tg   = lane & 3;

    for (int i = tid; i < 6 * 64; i += 256) sW1[i] = W1[i];
    if (tid < 64) { sb1[tid] = b1[tid]; sb2[tid] = b2[tid]; }
    for (int i = tid; i < 2048; i += 256) {
        int ks = i >> 8;
        int tt = (i >> 6) & 3;
        int n  = i & 63;
        float w0 = W2[(8 * ks + tt) * 64 + n];
        float w1 = W2[(8 * ks + tt + 4) * 64 + n];
        sW2p[(4 * ks + tt) * W2PS + n] = make_uint2(__float_as_uint(w0), __float_as_uint(w1));
    }

    const int m0 = blockIdx.x * 256;
    {
        int m = m0 + tid;
        int src = 0, dst = -1;
        if (m < N_MSG) {
            if (m < N_EDGES) { src = ei[m]; dst = ei[N_EDGES + m]; }
            else             { src = dst = m - N_EDGES; }   // self-loop
        }
        sdst[tid] = dst;
        float* ip = sIn + tid * 9;
        if (dst >= 0) {
            ip[0] = x[src * 3 + 0];
            ip[1] = x[src * 3 + 1];
            ip[2] = x[src * 3 + 2];
            ip[3] = pos[src * 3 + 0] - pos[dst * 3 + 0];
            ip[4] = pos[src * 3 + 1] - pos[dst * 3 + 1];
            ip[5] = pos[src * 3 + 2] - pos[dst * 3 + 2];
        } else {
            #pragma unroll
            for (int i = 0; i < 6; i++) ip[i] = 0.0f;
        }
    }
    __syncthreads();

    const int mrow = warp * 32;
    int mr[4];
    mr[0] = mrow + g; mr[1] = mr[0] + 8; mr[2] = mr[0] + 16; mr[3] = mr[0] + 24;

    float in[4][6];
    int d[4];
    #pragma unroll
    for (int r = 0; r < 4; r++) {
        d[r] = sdst[mr[r]];
        #pragma unroll
        for (int i = 0; i < 6; i++) in[r][i] = sIn[mr[r] * 9 + i];
    }

    #pragma unroll
    for (int pass = 0; pass < 2; pass++) {
        float c[2][4][4];
        #pragma unroll
        for (int mt = 0; mt < 2; mt++)
            #pragma unroll
            for (int nt = 0; nt < 4; nt++)
                #pragma unroll
                for (int q = 0; q < 4; q++) c[mt][nt][q] = 0.0f;

        #pragma unroll
        for (int ks = 0; ks < 8; ks++) {
            const int ka = 8 * ks + tg;
            const int kb = ka + 4;
            const float bka = sb1[ka], bkb = sb1[kb];
            float hA[4], hB[4];
            #pragma unroll
            for (int r = 0; r < 4; r++) { hA[r] = bka; hB[r] = bkb; }
            #pragma unroll
            for (int i = 0; i < 6; i++) {
                float wA = sW1[i * 64 + ka];
                float wB = sW1[i * 64 + kb];
                #pragma unroll
                for (int r = 0; r < 4; r++) {
                    hA[r] = fmaf(in[r][i], wA, hA[r]);
                    hB[r] = fmaf(in[r][i], wB, hB[r]);
                }
            }
            unsigned int af[2][4];
            #pragma unroll
            for (int mt = 0; mt < 2; mt++) {
                af[mt][0] = __float_as_uint(fmaxf(hA[2 * mt    ], 0.0f));
                af[mt][1] = __float_as_uint(fmaxf(hA[2 * mt + 1], 0.0f));
                af[mt][2] = __float_as_uint(fmaxf(hB[2 * mt    ], 0.0f));
                af[mt][3] = __float_as_uint(fmaxf(hB[2 * mt + 1], 0.0f));
            }
            const uint2* wrow = sW2p + (4 * ks + tg) * W2PS + pass * 32;
            #pragma unroll
            for (int nt = 0; nt < 4; nt++) {
                uint2 b = wrow[nt * 8 + g];
                mma_tf32(c[0][nt], af[0][0], af[0][1], af[0][2], af[0][3], b.x, b.y);
                mma_tf32(c[1][nt], af[1][0], af[1][1], af[1][2], af[1][3], b.x, b.y);
            }
        }

        // epilogue for this pass's 32 channels
        #pragma unroll
        for (int mt = 0; mt < 2; mt++) {
            const int d0 = d[2 * mt];
            const int d1 = d[2 * mt + 1];
            #pragma unroll
            for (int nt = 0; nt < 4; nt++) {
                int ch = pass * 32 + nt * 8 + 2 * tg;
                float bv0 = sb2[ch], bv1 = sb2[ch + 1];
                if (d0 >= 0) {
                    atomicMax(g_agg_u + (size_t)d0 * 64 + ch,     fmap(c[mt][nt][0] + bv0));
                    atomicMax(g_agg_u + (size_t)d0 * 64 + ch + 1, fmap(c[mt][nt][1] + bv1));
                }
                if (d1 >= 0) {
                    atomicMax(g_agg_u + (size_t)d1 * 64 + ch,     fmap(c[mt][nt][2] + bv0));
                    atomicMax(g_agg_u + (size_t)d1 * 64 + ch + 1, fmap(c[mt][nt][3] + bv1));
                }
            }
        }
    }
}

// ---------------- fused: g1=relu(agg@W3+b3); relu(g1@W4+b4)@W5+b5 -> relu -> fc -> log_softmax ----------------
#define FS_G1 0                     // [128m][132] g1 tile (computed in-kernel)
#define FS_B  16896                 // W3 [64][136] / W4 chunk [128k][136] / W5 chunk [128k][72] / Wf
#define FS_T  34304                 // agg tile [128m][68] / relu tile [128m][132] / g3 tile [128m][68]
#define FS_B4 51200                 // [128] bias scratch
#define FS_B5 51328                 // [64]
#define FS_WORDS 51392              // 205,568 bytes dynamic smem

__global__ __launch_bounds__(256) void k_fused_mid(
    const unsigned int* __restrict__ Agg, // mapped-uint agg [nrows,64]
    const float* __restrict__ W3,   // [64,128]
    const float* __restrict__ b3,   // [128]
    const float* __restrict__ W4,   // [128,1024]
    const float* __restrict__ b4,   // [1024]
    const float* __restrict__ W5,   // [1024,64]
    const float* __restrict__ b5,   // [64]
    const float* __restrict__ Wf,   // [64,40]
    const float* __restrict__ bf,   // [40]
    float* __restrict__ out,        // [nrows,40]
    int nrows)
{
    extern __shared__ unsigned int sm[];
    const int tid  = threadIdx.x;
    const int lane = tid & 31;
    const int warp = tid >> 5;
    const int wm   = warp >> 1;
    const int wn   = warp & 1;
    const int g    = lane >> 2;
    const int tg   = lane & 3;
    const int mrow = wm * 32;
    const int n0   = blockIdx.x * 128;

    // ---- stage agg tile [128][68] (unmapped -> raw f32 bits) into FS_T ----
    #pragma unroll
    for (int i = 0; i < 32; i++) {
        int idx = tid + i * 256;          // 0..8191
        int mm = idx >> 6, q = idx & 63;
        int row = n0 + mm;
        float v = 0.0f;
        if (row < nrows) v = funmap(Agg[(size_t)row * 64 + q]);
        sm[FS_T + mm * 68 + q] = __float_as_uint(v);
    }
    // ---- stage W3 [64][136] into FS_B, b3 -> FS_B4 ----
    #pragma unroll
    for (int i = 0; i < 8; i++) {
        int idx = tid + i * 256;          // 0..2047 uint4
        int k = idx >> 5, q = idx & 31;
        *(uint4*)&sm[FS_B + k * 136 + q * 4] = *(const uint4*)&W3[(size_t)k * 128 + q * 4];
    }
    if (tid < 128) sm[FS_B4 + tid] = __float_as_uint(b3[tid]);
    if (tid < 64)  sm[FS_B5 + tid] = __float_as_uint(b5[tid]);
    __syncthreads();

    // ---- pre-stage: g1_tile = relu(agg @ W3 + b3) -> FS_G1 [128][132] ----
    {
        float acc[2][8][4];
        #pragma unroll
        for (int mt = 0; mt < 2; mt++)
            #pragma unroll
            for (int nt = 0; nt < 8; nt++)
                #pragma unroll
                for (int q = 0; q < 4; q++) acc[mt][nt][q] = 0.0f;

        #pragma unroll
        for (int ks = 0; ks < 8; ks++) {
            const int k0 = ks * 8;
            unsigned int a[2][4];
            #pragma unroll
            for (int mt = 0; mt < 2; mt++) {
                int mr = mrow + mt * 16;
                a[mt][0] = sm[FS_T + (mr + g    ) * 68 + k0 + tg    ];
                a[mt][1] = sm[FS_T + (mr + g + 8) * 68 + k0 + tg    ];
                a[mt][2] = sm[FS_T + (mr + g    ) * 68 + k0 + tg + 4];
                a[mt][3] = sm[FS_T + (mr + g + 8) * 68 + k0 + tg + 4];
            }
            #pragma unroll
            for (int nt = 0; nt < 8; nt++) {
                int nc = wn * 64 + nt * 8 + g;
                unsigned int b0 = sm[FS_B + (k0 + tg    ) * 136 + nc];
                unsigned int b1 = sm[FS_B + (k0 + tg + 4) * 136 + nc];
                #pragma unroll
                for (int mt = 0; mt < 2; mt++)
                    mma_tf32(acc[mt][nt], a[mt][0], a[mt][1], a[mt][2], a[mt][3], b0, b1);
            }
        }
        __syncthreads();   // done reading FS_T(agg) & FS_B(W3)

        #pragma unroll
        for (int nt = 0; nt < 8; nt++) {
            int col = wn * 64 + nt * 8 + 2 * tg;
            float bv0 = __uint_as_float(sm[FS_B4 + col]);
            float bv1 = __uint_as_float(sm[FS_B4 + col + 1]);
            #pragma unroll
            for (int mt = 0; mt < 2; mt++) {
                int r0 = mrow + mt * 16 + g;
                int r1 = r0 + 8;
                sm[FS_G1 + r0 * 132 + col    ] = __float_as_uint(fmaxf(acc[mt][nt][0] + bv0, 0.0f));
                sm[FS_G1 + r0 * 132 + col + 1] = __float_as_uint(fmaxf(acc[mt][nt][1] + bv1, 0.0f));
                sm[FS_G1 + r1 * 132 + col    ] = __float_as_uint(fmaxf(acc[mt][nt][2] + bv0, 0.0f));
                sm[FS_G1 + r1 * 132 + col + 1] = __float_as_uint(fmaxf(acc[mt][nt][3] + bv1, 0.0f));
            }
        }
    }

    float acc2[2][4][4];
    #pragma unroll
    for (int mt = 0; mt < 2; mt++)
        #pragma unroll
        for (int nt = 0; nt < 4; nt++)
            #pragma unroll
            for (int q = 0; q < 4; q++) acc2[mt][nt][q] = 0.0f;

    for (int cch = 0; cch < 8; cch++) {
        __syncthreads();
        #pragma unroll
        for (int i = 0; i < 16; i++) {
            int idx = tid + i * 256;
            int k = idx >> 5, q = idx & 31;
            *(uint4*)&sm[FS_B + k * 136 + q * 4] =
                *(const uint4*)&W4[(size_t)k * 1024 + cch * 128 + q * 4];
        }
        if (tid < 128) sm[FS_B4 + tid] = __float_as_uint(b4[cch * 128 + tid]);
        __syncthreads();

        float acc1[2][8][4];
        #pragma unroll
        for (int mt = 0; mt < 2; mt++)
            #pragma unroll
            for (int nt = 0; nt < 8; nt++)
                #pragma unroll
                for (int q = 0; q < 4; q++) acc1[mt][nt][q] = 0.0f;

        #pragma unroll
        for (int ks = 0; ks < 16; ks++) {
            const int k0 = ks * 8;
            unsigned int a[2][4];
            #pragma unroll
            for (int mt = 0; mt < 2; mt++) {
                int mr = mrow + mt * 16;
                a[mt][0] = sm[FS_G1 + (mr + g    ) * 132 + k0 + tg    ];
                a[mt][1] = sm[FS_G1 + (mr + g + 8) * 132 + k0 + tg    ];
                a[mt][2] = sm[FS_G1 + (mr + g    ) * 132 + k0 + tg + 4];
                a[mt][3] = sm[FS_G1 + (mr + g + 8) * 132 + k0 + tg + 4];
            }
            #pragma unroll
            for (int nt = 0; nt < 8; nt++) {
                int nc = wn * 64 + nt * 8 + g;
                unsigned int b0 = sm[FS_B + (k0 + tg    ) * 136 + nc];
                unsigned int b1 = sm[FS_B + (k0 + tg + 4) * 136 + nc];
                #pragma unroll
                for (int mt = 0; mt < 2; mt++)
                    mma_tf32(acc1[mt][nt], a[mt][0], a[mt][1], a[mt][2], a[mt][3], b0, b1);
            }
        }
        __syncthreads();

        #pragma unroll
        for (int nt = 0; nt < 8; nt++) {
            int col = wn * 64 + nt * 8 + 2 * tg;
            float bv0 = __uint_as_float(sm[FS_B4 + col]);
            float bv1 = __uint_as_float(sm[FS_B4 + col + 1]);
            #pragma unroll
            for (int mt = 0; mt < 2; mt++) {
                int r0 = mrow + mt * 16 + g;
                int r1 = r0 + 8;
                sm[FS_T + r0 * 132 + col    ] = __float_as_uint(fmaxf(acc1[mt][nt][0] + bv0, 0.0f));
                sm[FS_T + r0 * 132 + col + 1] = __float_as_uint(fmaxf(acc1[mt][nt][1] + bv1, 0.0f));
                sm[FS_T + r1 * 132 + col    ] = __float_as_uint(fmaxf(acc1[mt][nt][2] + bv0, 0.0f));
                sm[FS_T + r1 * 132 + col + 1] = __float_as_uint(fmaxf(acc1[mt][nt][3] + bv1, 0.0f));
            }
        }
        #pragma unroll
        for (int i = 0; i < 8; i++) {
            int idx = tid + i * 256;
            int k = idx >> 4, q = idx & 15;
            *(uint4*)&sm[FS_B + k * 72 + q * 4] =
                *(const uint4*)&W5[(size_t)(cch * 128 + k) * 64 + q * 4];
        }
        __syncthreads();

        #pragma unroll
        for (int ks = 0; ks < 16; ks++) {
            const int k0 = ks * 8;
            unsigned int a[2][4];
            #pragma unroll
            for (int mt = 0; mt < 2; mt++) {
                int mr = mrow + mt * 16;
                a[mt][0] = sm[FS_T + (mr + g    ) * 132 + k0 + tg    ];
                a[mt][1] = sm[FS_T + (mr + g + 8) * 132 + k0 + tg    ];
                a[mt][2] = sm[FS_T + (mr + g    ) * 132 + k0 + tg + 4];
                a[mt][3] = sm[FS_T + (mr + g + 8) * 132 + k0 + tg + 4];
            }
            #pragma unroll
            for (int nt = 0; nt < 4; nt++) {
                int nc = wn * 32 + nt * 8 + g;
                unsigned int b0 = sm[FS_B + (k0 + tg    ) * 72 + nc];
                unsigned int b1 = sm[FS_B + (k0 + tg + 4) * 72 + nc];
                #pragma unroll
                for (int mt = 0; mt < 2; mt++)
                    mma_tf32(acc2[mt][nt], a[mt][0], a[mt][1], a[mt][2], a[mt][3], b0, b1);
            }
        }
    }
    __syncthreads();

    for (int i = tid; i < 64 * 40; i += 256) sm[FS_B + i] = __float_as_uint(Wf[i]);
    if (tid < 40) sm[FS_B4 + tid] = __float_as_uint(bf[tid]);
    #pragma unroll
    for (int nt = 0; nt < 4; nt++) {
        int col = wn * 32 + nt * 8 + 2 * tg;
        float bv0 = __uint_as_float(sm[FS_B5 + col]);
        float bv1 = __uint_as_float(sm[FS_B5 + col + 1]);
        #pragma unroll
        for (int mt = 0; mt < 2; mt++) {
            int r0 = mrow + mt * 16 + g;
            int r1 = r0 + 8;
            sm[FS_T + r0 * 68 + col    ] = __float_as_uint(acc2[mt][nt][0] + bv0);
            sm[FS_T + r0 * 68 + col + 1] = __float_as_uint(acc2[mt][nt][1] + bv1);
            sm[FS_T + r1 * 68 + col    ] = __float_as_uint(acc2[mt][nt][2] + bv0);
            sm[FS_T + r1 * 68 + col + 1] = __float_as_uint(acc2[mt][nt][3] + bv1);
        }
    }
    __syncthreads();

    for (int j = 0; j < 16; j++) {
        int nl = warp * 16 + j;
        int node = n0 + nl;
        if (node >= nrows) break;
        float v0 = __uint_as_float(sm[FS_B4 + lane]);
        float v1 = (lane < 8) ? __uint_as_float(sm[FS_B4 + lane + 32]) : -FLT_MAX;
        #pragma unroll
        for (int k = 0; k < 64; k++) {
            float a = fmaxf(__uint_as_float(sm[FS_T + nl * 68 + k]), 0.0f);
            float w0 = __uint_as_float(sm[FS_B + k * 40 + lane]);
            v0 = fmaf(a, w0, v0);
            if (lane < 8) {
                float w1 = __uint_as_float(sm[FS_B + k * 40 + lane + 32]);
                v1 = fmaf(a, w1, v1);
            }
        }
        float mx = fmaxf(v0, v1);
        #pragma unroll
        for (int off = 16; off > 0; off >>= 1)
            mx = fmaxf(mx, __shfl_xor_sync(0xFFFFFFFFu, mx, off));
        float s = __expf(v0 - mx) + ((lane < 8) ? __expf(v1 - mx) : 0.0f);
        #pragma unroll
        for (int off = 16; off > 0; off >>= 1)
            s += __shfl_xor_sync(0xFFFFFFFFu, s, off);
        float ls = __logf(s);
        float* op = out + (size_t)node * C_OUT;
        op[lane] = v0 - mx - ls;
        if (lane < 8) op[lane + 32] = v1 - mx - ls;
    }
}

// ---------------- launcher ----------------
extern "C" void kernel_launch(void* const* d_in, const int* in_sizes, int n_in,
                              void* d_out, int out_size) {
    const float* x   = (const float*)d_in[0];
    const float* pos = (const float*)d_in[1];
    const int*   ei  = (const int*)d_in[2];
    const float* W1 = (const float*)d_in[3];
    const float* b1 = (const float*)d_in[4];
    const float* W2 = (const float*)d_in[5];
    const float* b2 = (const float*)d_in[6];
    const float* W3 = (const float*)d_in[7];
    const float* b3 = (const float*)d_in[8];
    const float* W4 = (const float*)d_in[9];
    const float* b4 = (const float*)d_in[10];
    const float* W5 = (const float*)d_in[11];
    const float* b5 = (const float*)d_in[12];
    const float* Wf = (const float*)d_in[13];
    const float* bf = (const float*)d_in[14];
    float* out = (float*)d_out;

    void* aggp = nullptr;
    cudaGetSymbolAddress(&aggp, g_agg_u);

    cudaFuncSetAttribute(k_fused_mid, cudaFuncAttributeMaxDynamicSharedMemorySize,
                         FS_WORDS * 4);

    // mapped-uint 0 is below every mapped float -> -inf init
    cudaMemsetAsync(aggp, 0, (size_t)N_NODES * 64 * sizeof(unsigned int));

    k_edge_v4<<<(N_MSG + 255) / 256, 256>>>(x, pos, ei, W1, b1, W2, b2);

    k_fused_mid<<<(N_NODES + 127) / 128, 256, FS_WORDS * 4>>>(
        (const unsigned int*)aggp, W3, b3, W4, b4, W5, b5, Wf, bf, out, N_NODES);
}

// round 15
// speedup vs baseline: 1.9534x; 1.0065x over previous
#include <cuda_runtime.h>
#include <cuda_bf16.h>
#include <math.h>
#include <float.h>

#define N_NODES 50000
#define N_EDGES 1600000
#define N_MSG   (N_EDGES + N_NODES)
#define C_OUT   40

// ---------------- scratch (static device globals; no allocation) ----------------
__device__ __align__(256) unsigned int g_agg_u[N_NODES * 64]; // mapped-uint segment-max

// ---------------- helpers ----------------
__device__ __forceinline__ unsigned int fmap(float v) {
    unsigned int k = __float_as_uint(v);
    return ((int)k < 0) ? ~k : (k | 0x80000000u);
}
__device__ __forceinline__ float funmap(unsigned int k) {
    return (k & 0x80000000u) ? __uint_as_float(k & 0x7FFFFFFFu)
                             : __uint_as_float(~k);
}
// tf32 mma reads only bits [31:13]; raw f32 bits == RZ-truncated tf32.
__device__ __forceinline__ void mma_tf32(float (&c)[4],
                                         unsigned int a0, unsigned int a1,
                                         unsigned int a2, unsigned int a3,
                                         unsigned int b0, unsigned int b1) {
    asm volatile(
        "mma.sync.aligned.m16n8k8.row.col.f32.tf32.tf32.f32 "
        "{%0,%1,%2,%3}, {%4,%5,%6,%7}, {%8,%9}, {%0,%1,%2,%3};"
        : "+f"(c[0]), "+f"(c[1]), "+f"(c[2]), "+f"(c[3])
        : "r"(a0), "r"(a1), "r"(a2), "r"(a3), "r"(b0), "r"(b1));
}

// ---------------- kernel 1: edge MLP v4 (unchanged from R14) ----------------
#define W2PS 68
__global__ __launch_bounds__(256, 3) void k_edge_v4(
    const float* __restrict__ x,
    const float* __restrict__ pos,
    const int*   __restrict__ ei,
    const float* __restrict__ W1,
    const float* __restrict__ b1,
    const float* __restrict__ W2,
    const float* __restrict__ b2)
{
    __shared__ float sW1[6 * 64];
    __shared__ float sb1[64];
    __shared__ float sb2[64];
    __shared__ uint2 sW2p[32 * W2PS];
    __shared__ float sIn[256 * 9];
    __shared__ int   sdst[256];

    const int tid  = threadIdx.x;
    const int lane = tid & 31;
    const int warp = tid >> 5;
    const int g    = lane >> 2;
    const int tg   = lane & 3;

    for (int i = tid; i < 6 * 64; i += 256) sW1[i] = W1[i];
    if (tid < 64) { sb1[tid] = b1[tid]; sb2[tid] = b2[tid]; }
    for (int i = tid; i < 2048; i += 256) {
        int ks = i >> 8;
        int tt = (i >> 6) & 3;
        int n  = i & 63;
        float w0 = W2[(8 * ks + tt) * 64 + n];
        float w1 = W2[(8 * ks + tt + 4) * 64 + n];
        sW2p[(4 * ks + tt) * W2PS + n] = make_uint2(__float_as_uint(w0), __float_as_uint(w1));
    }

    const int m0 = blockIdx.x * 256;
    {
        int m = m0 + tid;
        int src = 0, dst = -1;
        if (m < N_MSG) {
            if (m < N_EDGES) { src = ei[m]; dst = ei[N_EDGES + m]; }
            else             { src = dst = m - N_EDGES; }
        }
        sdst[tid] = dst;
        float* ip = sIn + tid * 9;
        if (dst >= 0) {
            ip[0] = x[src * 3 + 0];
            ip[1] = x[src * 3 + 1];
            ip[2] = x[src * 3 + 2];
            ip[3] = pos[src * 3 + 0] - pos[dst * 3 + 0];
            ip[4] = pos[src * 3 + 1] - pos[dst * 3 + 1];
            ip[5] = pos[src * 3 + 2] - pos[dst * 3 + 2];
        } else {
            #pragma unroll
            for (int i = 0; i < 6; i++) ip[i] = 0.0f;
        }
    }
    __syncthreads();

    const int mrow = warp * 32;
    int mr[4];
    mr[0] = mrow + g; mr[1] = mr[0] + 8; mr[2] = mr[0] + 16; mr[3] = mr[0] + 24;

    float in[4][6];
    int d[4];
    #pragma unroll
    for (int r = 0; r < 4; r++) {
        d[r] = sdst[mr[r]];
        #pragma unroll
        for (int i = 0; i < 6; i++) in[r][i] = sIn[mr[r] * 9 + i];
    }

    #pragma unroll
    for (int pass = 0; pass < 2; pass++) {
        float c[2][4][4];
        #pragma unroll
        for (int mt = 0; mt < 2; mt++)
            #pragma unroll
            for (int nt = 0; nt < 4; nt++)
                #pragma unroll
                for (int q = 0; q < 4; q++) c[mt][nt][q] = 0.0f;

        #pragma unroll
        for (int ks = 0; ks < 8; ks++) {
            const int ka = 8 * ks + tg;
            const int kb = ka + 4;
            const float bka = sb1[ka], bkb = sb1[kb];
            float hA[4], hB[4];
            #pragma unroll
            for (int r = 0; r < 4; r++) { hA[r] = bka; hB[r] = bkb; }
            #pragma unroll
            for (int i = 0; i < 6; i++) {
                float wA = sW1[i * 64 + ka];
                float wB = sW1[i * 64 + kb];
                #pragma unroll
                for (int r = 0; r < 4; r++) {
                    hA[r] = fmaf(in[r][i], wA, hA[r]);
                    hB[r] = fmaf(in[r][i], wB, hB[r]);
                }
            }
            unsigned int af[2][4];
            #pragma unroll
            for (int mt = 0; mt < 2; mt++) {
                af[mt][0] = __float_as_uint(fmaxf(hA[2 * mt    ], 0.0f));
                af[mt][1] = __float_as_uint(fmaxf(hA[2 * mt + 1], 0.0f));
                af[mt][2] = __float_as_uint(fmaxf(hB[2 * mt    ], 0.0f));
                af[mt][3] = __float_as_uint(fmaxf(hB[2 * mt + 1], 0.0f));
            }
            const uint2* wrow = sW2p + (4 * ks + tg) * W2PS + pass * 32;
            #pragma unroll
            for (int nt = 0; nt < 4; nt++) {
                uint2 b = wrow[nt * 8 + g];
                mma_tf32(c[0][nt], af[0][0], af[0][1], af[0][2], af[0][3], b.x, b.y);
                mma_tf32(c[1][nt], af[1][0], af[1][1], af[1][2], af[1][3], b.x, b.y);
            }
        }

        #pragma unroll
        for (int mt = 0; mt < 2; mt++) {
            const int d0 = d[2 * mt];
            const int d1 = d[2 * mt + 1];
            #pragma unroll
            for (int nt = 0; nt < 4; nt++) {
                int ch = pass * 32 + nt * 8 + 2 * tg;
                float bv0 = sb2[ch], bv1 = sb2[ch + 1];
                if (d0 >= 0) {
                    atomicMax(g_agg_u + (size_t)d0 * 64 + ch,     fmap(c[mt][nt][0] + bv0));
                    atomicMax(g_agg_u + (size_t)d0 * 64 + ch + 1, fmap(c[mt][nt][1] + bv1));
                }
                if (d1 >= 0) {
                    atomicMax(g_agg_u + (size_t)d1 * 64 + ch,     fmap(c[mt][nt][2] + bv0));
                    atomicMax(g_agg_u + (size_t)d1 * 64 + ch + 1, fmap(c[mt][nt][3] + bv1));
                }
            }
        }
    }
}

// ---------------- fused mid, 512 threads / 16 warps (4M x 4N) ----------------
#define FS_G1 0                     // [128m][132]
#define FS_B  16896                 // W3 [64][136] / W4 chunk [128k][136] / W5 chunk [128k][72] / Wf
#define FS_T  34304                 // agg [128m][68] / relu tile [128m][132] / g3 [128m][68]
#define FS_B4 51200                 // [128] bias scratch
#define FS_B5 51328                 // [64]
#define FS_WORDS 51392              // 205,568 bytes dynamic smem
#define FT 512

__global__ __launch_bounds__(FT) void k_fused_mid(
    const unsigned int* __restrict__ Agg, // mapped-uint agg [nrows,64]
    const float* __restrict__ W3,   // [64,128]
    const float* __restrict__ b3,   // [128]
    const float* __restrict__ W4,   // [128,1024]
    const float* __restrict__ b4,   // [1024]
    const float* __restrict__ W5,   // [1024,64]
    const float* __restrict__ b5,   // [64]
    const float* __restrict__ Wf,   // [64,40]
    const float* __restrict__ bf,   // [40]
    float* __restrict__ out,        // [nrows,40]
    int nrows)
{
    extern __shared__ unsigned int sm[];
    const int tid  = threadIdx.x;
    const int lane = tid & 31;
    const int warp = tid >> 5;          // 0..15
    const int wm   = warp >> 2;         // 0..3 (M groups of 32 rows)
    const int wn   = warp & 3;          // 0..3 (N groups)
    const int g    = lane >> 2;
    const int tg   = lane & 3;
    const int mrow = wm * 32;
    const int n0   = blockIdx.x * 128;

    // ---- stage agg tile [128][68] (unmapped) into FS_T ----
    #pragma unroll
    for (int i = 0; i < 16; i++) {
        int idx = tid + i * FT;           // 0..8191
        int mm = idx >> 6, q = idx & 63;
        int row = n0 + mm;
        float v = 0.0f;
        if (row < nrows) v = funmap(Agg[(size_t)row * 64 + q]);
        sm[FS_T + mm * 68 + q] = __float_as_uint(v);
    }
    // ---- stage W3 [64][136], b3, b5 ----
    #pragma unroll
    for (int i = 0; i < 4; i++) {
        int idx = tid + i * FT;           // 0..2047 uint4
        int k = idx >> 5, q = idx & 31;
        *(uint4*)&sm[FS_B + k * 136 + q * 4] = *(const uint4*)&W3[(size_t)k * 128 + q * 4];
    }
    if (tid < 128) sm[FS_B4 + tid] = __float_as_uint(b3[tid]);
    if (tid >= 128 && tid < 192) sm[FS_B5 + tid - 128] = __float_as_uint(b5[tid - 128]);
    __syncthreads();

    // ---- pre-stage: g1 = relu(agg @ W3 + b3) -> FS_G1 [128][132] ----
    // warp: rows mrow+mt*16, cols wn*32 + nt*8 (nt 0..3), K=64
    {
        float acc[2][4][4];
        #pragma unroll
        for (int mt = 0; mt < 2; mt++)
            #pragma unroll
            for (int nt = 0; nt < 4; nt++)
                #pragma unroll
                for (int q = 0; q < 4; q++) acc[mt][nt][q] = 0.0f;

        #pragma unroll
        for (int ks = 0; ks < 8; ks++) {
            const int k0 = ks * 8;
            unsigned int a[2][4];
            #pragma unroll
            for (int mt = 0; mt < 2; mt++) {
                int mr = mrow + mt * 16;
                a[mt][0] = sm[FS_T + (mr + g    ) * 68 + k0 + tg    ];
                a[mt][1] = sm[FS_T + (mr + g + 8) * 68 + k0 + tg    ];
                a[mt][2] = sm[FS_T + (mr + g    ) * 68 + k0 + tg + 4];
                a[mt][3] = sm[FS_T + (mr + g + 8) * 68 + k0 + tg + 4];
            }
            #pragma unroll
            for (int nt = 0; nt < 4; nt++) {
                int nc = wn * 32 + nt * 8 + g;
                unsigned int b0 = sm[FS_B + (k0 + tg    ) * 136 + nc];
                unsigned int b1 = sm[FS_B + (k0 + tg + 4) * 136 + nc];
                #pragma unroll
                for (int mt = 0; mt < 2; mt++)
                    mma_tf32(acc[mt][nt], a[mt][0], a[mt][1], a[mt][2], a[mt][3], b0, b1);
            }
        }
        __syncthreads();   // done reading FS_T(agg) & FS_B(W3)

        #pragma unroll
        for (int nt = 0; nt < 4; nt++) {
            int col = wn * 32 + nt * 8 + 2 * tg;
            float bv0 = __uint_as_float(sm[FS_B4 + col]);
            float bv1 = __uint_as_float(sm[FS_B4 + col + 1]);
            #pragma unroll
            for (int mt = 0; mt < 2; mt++) {
                int r0 = mrow + mt * 16 + g;
                int r1 = r0 + 8;
                sm[FS_G1 + r0 * 132 + col    ] = __float_as_uint(fmaxf(acc[mt][nt][0] + bv0, 0.0f));
                sm[FS_G1 + r0 * 132 + col + 1] = __float_as_uint(fmaxf(acc[mt][nt][1] + bv1, 0.0f));
                sm[FS_G1 + r1 * 132 + col    ] = __float_as_uint(fmaxf(acc[mt][nt][2] + bv0, 0.0f));
                sm[FS_G1 + r1 * 132 + col + 1] = __float_as_uint(fmaxf(acc[mt][nt][3] + bv1, 0.0f));
            }
        }
    }

    float acc2[2][2][4];   // rows mrow+mt*16, cols wn*16 + nt*8 (nt 0..1)
    #pragma unroll
    for (int mt = 0; mt < 2; mt++)
        #pragma unroll
        for (int nt = 0; nt < 2; nt++)
            #pragma unroll
            for (int q = 0; q < 4; q++) acc2[mt][nt][q] = 0.0f;

    for (int cch = 0; cch < 8; cch++) {
        __syncthreads();
        #pragma unroll
        for (int i = 0; i < 8; i++) {
            int idx = tid + i * FT;         // 0..4095 uint4
            int k = idx >> 5, q = idx & 31;
            *(uint4*)&sm[FS_B + k * 136 + q * 4] =
                *(const uint4*)&W4[(size_t)k * 1024 + cch * 128 + q * 4];
        }
        if (tid < 128) sm[FS_B4 + tid] = __float_as_uint(b4[cch * 128 + tid]);
        __syncthreads();

        // ---- stage1: t = g1 @ W4chunk (128x128, K=128); warp cols wn*32+nt*8 ----
        float acc1[2][4][4];
        #pragma unroll
        for (int mt = 0; mt < 2; mt++)
            #pragma unroll
            for (int nt = 0; nt < 4; nt++)
                #pragma unroll
                for (int q = 0; q < 4; q++) acc1[mt][nt][q] = 0.0f;

        #pragma unroll
        for (int ks = 0; ks < 16; ks++) {
            const int k0 = ks * 8;
            unsigned int a[2][4];
            #pragma unroll
            for (int mt = 0; mt < 2; mt++) {
                int mr = mrow + mt * 16;
                a[mt][0] = sm[FS_G1 + (mr + g    ) * 132 + k0 + tg    ];
                a[mt][1] = sm[FS_G1 + (mr + g + 8) * 132 + k0 + tg    ];
                a[mt][2] = sm[FS_G1 + (mr + g    ) * 132 + k0 + tg + 4];
                a[mt][3] = sm[FS_G1 + (mr + g + 8) * 132 + k0 + tg + 4];
            }
            #pragma unroll
            for (int nt = 0; nt < 4; nt++) {
                int nc = wn * 32 + nt * 8 + g;
                unsigned int b0 = sm[FS_B + (k0 + tg    ) * 136 + nc];
                unsigned int b1 = sm[FS_B + (k0 + tg + 4) * 136 + nc];
                #pragma unroll
                for (int mt = 0; mt < 2; mt++)
                    mma_tf32(acc1[mt][nt], a[mt][0], a[mt][1], a[mt][2], a[mt][3], b0, b1);
            }
        }
        __syncthreads();

        // ---- bias + relu -> FS_T [128][132]; reload FS_B with W5 chunk ----
        #pragma unroll
        for (int nt = 0; nt < 4; nt++) {
            int col = wn * 32 + nt * 8 + 2 * tg;
            float bv0 = __uint_as_float(sm[FS_B4 + col]);
            float bv1 = __uint_as_float(sm[FS_B4 + col + 1]);
            #pragma unroll
            for (int mt = 0; mt < 2; mt++) {
                int r0 = mrow + mt * 16 + g;
                int r1 = r0 + 8;
                sm[FS_T + r0 * 132 + col    ] = __float_as_uint(fmaxf(acc1[mt][nt][0] + bv0, 0.0f));
                sm[FS_T + r0 * 132 + col + 1] = __float_as_uint(fmaxf(acc1[mt][nt][1] + bv1, 0.0f));
                sm[FS_T + r1 * 132 + col    ] = __float_as_uint(fmaxf(acc1[mt][nt][2] + bv0, 0.0f));
                sm[FS_T + r1 * 132 + col + 1] = __float_as_uint(fmaxf(acc1[mt][nt][3] + bv1, 0.0f));
            }
        }
        #pragma unroll
        for (int i = 0; i < 4; i++) {
            int idx = tid + i * FT;         // 0..2047 uint4
            int k = idx >> 4, q = idx & 15;
            *(uint4*)&sm[FS_B + k * 72 + q * 4] =
                *(const uint4*)&W5[(size_t)(cch * 128 + k) * 64 + q * 4];
        }
        __syncthreads();

        // ---- stage2: acc2 += t @ W5chunk (128x64, K=128); warp cols wn*16+nt*8 ----
        #pragma unroll
        for (int ks = 0; ks < 16; ks++) {
            const int k0 = ks * 8;
            unsigned int a[2][4];
            #pragma unroll
            for (int mt = 0; mt < 2; mt++) {
                int mr = mrow + mt * 16;
                a[mt][0] = sm[FS_T + (mr + g    ) * 132 + k0 + tg    ];
                a[mt][1] = sm[FS_T + (mr + g + 8) * 132 + k0 + tg    ];
                a[mt][2] = sm[FS_T + (mr + g    ) * 132 + k0 + tg + 4];
                a[mt][3] = sm[FS_T + (mr + g + 8) * 132 + k0 + tg + 4];
            }
            #pragma unroll
            for (int nt = 0; nt < 2; nt++) {
                int nc = wn * 16 + nt * 8 + g;
                unsigned int b0 = sm[FS_B + (k0 + tg    ) * 72 + nc];
                unsigned int b1 = sm[FS_B + (k0 + tg + 4) * 72 + nc];
                #pragma unroll
                for (int mt = 0; mt < 2; mt++)
                    mma_tf32(acc2[mt][nt], a[mt][0], a[mt][1], a[mt][2], a[mt][3], b0, b1);
            }
        }
    }
    __syncthreads();

    // ---- load Wf/bf; stage g3 tile (+b5) into FS_T stride 68 ----
    for (int i = tid; i < 64 * 40; i += FT) sm[FS_B + i] = __float_as_uint(Wf[i]);
    if (tid < 40) sm[FS_B4 + tid] = __float_as_uint(bf[tid]);
    #pragma unroll
    for (int nt = 0; nt < 2; nt++) {
        int col = wn * 16 + nt * 8 + 2 * tg;
        float bv0 = __uint_as_float(sm[FS_B5 + col]);
        float bv1 = __uint_as_float(sm[FS_B5 + col + 1]);
        #pragma unroll
        for (int mt = 0; mt < 2; mt++) {
            int r0 = mrow + mt * 16 + g;
            int r1 = r0 + 8;
            sm[FS_T + r0 * 68 + col    ] = __float_as_uint(acc2[mt][nt][0] + bv0);
            sm[FS_T + r0 * 68 + col + 1] = __float_as_uint(acc2[mt][nt][1] + bv1);
            sm[FS_T + r1 * 68 + col    ] = __float_as_uint(acc2[mt][nt][2] + bv0);
            sm[FS_T + r1 * 68 + col + 1] = __float_as_uint(acc2[mt][nt][3] + bv1);
        }
    }
    __syncthreads();

    // ---- fc + log_softmax: 16 warps x 8 nodes ----
    for (int j = 0; j < 8; j++) {
        int nl = warp * 8 + j;
        int node = n0 + nl;
        if (node >= nrows) break;
        float v0 = __uint_as_float(sm[FS_B4 + lane]);
        float v1 = (lane < 8) ? __uint_as_float(sm[FS_B4 + lane + 32]) : -FLT_MAX;
        #pragma unroll
        for (int k = 0; k < 64; k++) {
            float a = fmaxf(__uint_as_float(sm[FS_T + nl * 68 + k]), 0.0f);
            float w0 = __uint_as_float(sm[FS_B + k * 40 + lane]);
            v0 = fmaf(a, w0, v0);
            if (lane < 8) {
                float w1 = __uint_as_float(sm[FS_B + k * 40 + lane + 32]);
                v1 = fmaf(a, w1, v1);
            }
        }
        float mx = fmaxf(v0, v1);
        #pragma unroll
        for (int off = 16; off > 0; off >>= 1)
            mx = fmaxf(mx, __shfl_xor_sync(0xFFFFFFFFu, mx, off));
        float s = __expf(v0 - mx) + ((lane < 8) ? __expf(v1 - mx) : 0.0f);
        #pragma unroll
        for (int off = 16; off > 0; off >>= 1)
            s += __shfl_xor_sync(0xFFFFFFFFu, s, off);
        float ls = __logf(s);
        float* op = out + (size_t)node * C_OUT;
        op[lane] = v0 - mx - ls;
        if (lane < 8) op[lane + 32] = v1 - mx - ls;
    }
}

// ---------------- launcher ----------------
extern "C" void kernel_launch(void* const* d_in, const int* in_sizes, int n_in,
                              void* d_out, int out_size) {
    const float* x   = (const float*)d_in[0];
    const float* pos = (const float*)d_in[1];
    const int*   ei  = (const int*)d_in[2];
    const float* W1 = (const float*)d_in[3];
    const float* b1 = (const float*)d_in[4];
    const float* W2 = (const float*)d_in[5];
    const float* b2 = (const float*)d_in[6];
    const float* W3 = (const float*)d_in[7];
    const float* b3 = (const float*)d_in[8];
    const float* W4 = (const float*)d_in[9];
    const float* b4 = (const float*)d_in[10];
    const float* W5 = (const float*)d_in[11];
    const float* b5 = (const float*)d_in[12];
    const float* Wf = (const float*)d_in[13];
    const float* bf = (const float*)d_in[14];
    float* out = (float*)d_out;

    void* aggp = nullptr;
    cudaGetSymbolAddress(&aggp, g_agg_u);

    cudaFuncSetAttribute(k_fused_mid, cudaFuncAttributeMaxDynamicSharedMemorySize,
                         FS_WORDS * 4);

    // mapped-uint 0 is below every mapped float -> -inf init
    cudaMemsetAsync(aggp, 0, (size_t)N_NODES * 64 * sizeof(unsigned int));

    k_edge_v4<<<(N_MSG + 255) / 256, 256>>>(x, pos, ei, W1, b1, W2, b2);

    k_fused_mid<<<(N_NODES + 127) / 128, FT, FS_WORDS * 4>>>(
        (const unsigned int*)aggp, W3, b3, W4, b4, W5, b5, Wf, bf, out, N_NODES);
}